// round 1
// baseline (speedup 1.0000x reference)
#include <cuda_runtime.h>
#include <cstdint>

#define B_ 4
#define T_ 4096
#define D_ 1024
#define H_ 16
#define HD_ 64
#define CAP_ 512
#define M_ 2048            // B_ * CAP_
#define DFF_ 2730
#define DFFP_ 2736         // padded to multiple of 16 for float4/K-alignment

// ---------------------------------------------------------------------------
// Workspace (single __device__ global; no allocations anywhere)
// ---------------------------------------------------------------------------
constexpr size_t OFF_SCORES = 0;
constexpr size_t OFF_XSEL   = OFF_SCORES + (size_t)B_ * T_;
constexpr size_t OFF_H      = OFF_XSEL   + (size_t)M_ * D_;
constexpr size_t OFF_QKV    = OFF_H      + (size_t)M_ * D_;
constexpr size_t OFF_S      = OFF_QKV    + (size_t)M_ * 3 * D_;
constexpr size_t OFF_ATTN   = OFF_S      + (size_t)B_ * H_ * CAP_ * CAP_;
constexpr size_t OFF_Y1     = OFF_ATTN   + (size_t)M_ * D_;
constexpr size_t OFF_H2     = OFF_Y1     + (size_t)M_ * D_;
constexpr size_t OFF_U1     = OFF_H2     + (size_t)M_ * D_;
constexpr size_t OFF_U2     = OFF_U1     + (size_t)M_ * DFFP_;
constexpr size_t OFF_U      = OFF_U2     + (size_t)M_ * DFFP_;
constexpr size_t OFF_W3P    = OFF_U      + (size_t)M_ * DFFP_;
constexpr size_t OFF_XPROC  = OFF_W3P    + (size_t)D_ * DFFP_;
constexpr size_t WS_TOTAL   = OFF_XPROC  + (size_t)M_ * D_;

__device__ __align__(256) float d_ws[WS_TOTAL];
__device__ int d_idx[M_];   // gathered token indices, [B][CAP]

// ---------------------------------------------------------------------------
// 1. Router: scores[b][t] = dot(x[b,t,:], w_router)   (one warp per token)
// ---------------------------------------------------------------------------
__global__ __launch_bounds__(256) void router_kernel(const float* __restrict__ x,
                                                     const float* __restrict__ wr)
{
    int warp = (blockIdx.x * blockDim.x + threadIdx.x) >> 5;
    int lane = threadIdx.x & 31;
    if (warp >= B_ * T_) return;
    const float4* xr  = (const float4*)(x + (size_t)warp * D_);
    const float4* wr4 = (const float4*)wr;
    float acc = 0.f;
    #pragma unroll
    for (int k = lane; k < D_ / 4; k += 32) {
        float4 a = xr[k], w = wr4[k];
        acc += a.x * w.x + a.y * w.y + a.z * w.z + a.w * w.w;
    }
    #pragma unroll
    for (int o = 16; o; o >>= 1) acc += __shfl_xor_sync(0xFFFFFFFFu, acc, o);
    if (lane == 0) d_ws[OFF_SCORES + warp] = acc;
}

// ---------------------------------------------------------------------------
// 2. Top-k via full bitonic sort of 4096 packed keys per batch.
//    key = (sortable_float(score) << 32) | (0xFFFFFFFF - idx)
//    Descending sort -> descending score, ties broken by smaller index first
//    (matches jax.lax.top_k / torch.topk semantics).
// ---------------------------------------------------------------------------
__global__ __launch_bounds__(1024) void topk_kernel()
{
    __shared__ unsigned long long key[T_];
    int b = blockIdx.x;
    for (int t = threadIdx.x; t < T_; t += 1024) {
        float s = d_ws[OFF_SCORES + (size_t)b * T_ + t];
        unsigned int u = __float_as_uint(s);
        u = (u & 0x80000000u) ? ~u : (u | 0x80000000u);   // order-preserving map
        key[t] = ((unsigned long long)u << 32) | (unsigned int)(0xFFFFFFFFu - (unsigned)t);
    }
    __syncthreads();
    for (int k = 2; k <= T_; k <<= 1) {
        for (int j = k >> 1; j > 0; j >>= 1) {
            for (int t = threadIdx.x; t < T_; t += 1024) {
                int l = t ^ j;
                if (l > t) {
                    unsigned long long a = key[t], c = key[l];
                    bool desc = ((t & k) == 0);
                    if (desc ? (a < c) : (a > c)) { key[t] = c; key[l] = a; }
                }
            }
            __syncthreads();
        }
    }
    for (int t = threadIdx.x; t < CAP_; t += 1024)
        d_idx[b * CAP_ + t] = (int)(0xFFFFFFFFu - (unsigned int)(key[t] & 0xFFFFFFFFu));
}

// ---------------------------------------------------------------------------
// Block reduce helper (256 threads)
// ---------------------------------------------------------------------------
__device__ __forceinline__ float block_reduce_sum_256(float v, float* red)
{
    #pragma unroll
    for (int o = 16; o; o >>= 1) v += __shfl_xor_sync(0xFFFFFFFFu, v, o);
    if ((threadIdx.x & 31) == 0) red[threadIdx.x >> 5] = v;
    __syncthreads();
    float tot = 0.f;
    #pragma unroll
    for (int w = 0; w < 8; w++) tot += red[w];
    return tot;
}

// ---------------------------------------------------------------------------
// 3. Gather selected tokens + RMSNorm (writes x_sel and h)
// ---------------------------------------------------------------------------
__global__ __launch_bounds__(256) void gather_rmsnorm_kernel(const float* __restrict__ x,
                                                             const float* __restrict__ g)
{
    __shared__ float red[8];
    int row = blockIdx.x;             // 0..2047
    int b = row >> 9;
    int t = d_idx[row];
    int tid = threadIdx.x;
    const float4* src = (const float4*)(x + ((size_t)b * T_ + t) * D_);
    float4 v = src[tid];
    float ss = v.x*v.x + v.y*v.y + v.z*v.z + v.w*v.w;
    float tot = block_reduce_sum_256(ss, red);
    float rinv = rsqrtf(tot * (1.f / D_) + 1e-6f);
    const float4* g4 = (const float4*)g;
    float4 gv = g4[tid];
    ((float4*)(d_ws + OFF_XSEL + (size_t)row * D_))[tid] = v;
    float4 o;
    o.x = v.x * rinv * gv.x; o.y = v.y * rinv * gv.y;
    o.z = v.z * rinv * gv.z; o.w = v.w * rinv * gv.w;
    ((float4*)(d_ws + OFF_H + (size_t)row * D_))[tid] = o;
}

// ---------------------------------------------------------------------------
// 4. RMSNorm of y1 -> h2
// ---------------------------------------------------------------------------
__global__ __launch_bounds__(256) void rmsnorm2_kernel(const float* __restrict__ g)
{
    __shared__ float red[8];
    int row = blockIdx.x;
    int tid = threadIdx.x;
    float4 v = ((const float4*)(d_ws + OFF_Y1 + (size_t)row * D_))[tid];
    float ss = v.x*v.x + v.y*v.y + v.z*v.z + v.w*v.w;
    float tot = block_reduce_sum_256(ss, red);
    float rinv = rsqrtf(tot * (1.f / D_) + 1e-6f);
    float4 gv = ((const float4*)g)[tid];
    float4 o;
    o.x = v.x * rinv * gv.x; o.y = v.y * rinv * gv.y;
    o.z = v.z * rinv * gv.z; o.w = v.w * rinv * gv.w;
    ((float4*)(d_ws + OFF_H2 + (size_t)row * D_))[tid] = o;
}

// ---------------------------------------------------------------------------
// 5. Generic SGEMM (NT):  C[m][n] = sum_k A[m][k] * B[n][k]  (+ ADD[m][n])
//    BM=BN=128, BK=8, 256 threads, 8x8 per thread.
//    Requires: M % 128 == 0, K % 8 == 0, K % 4 == 0 (float4 loads).
//    Handles N not multiple of 128 (zero-fill loads, guarded stores).
// ---------------------------------------------------------------------------
#define BM 128
#define BN 128
#define BK 8

__global__ __launch_bounds__(256) void sgemm_nt(const float* __restrict__ A,
                                                const float* __restrict__ Bw,
                                                float* __restrict__ C,
                                                const float* __restrict__ ADD,
                                                int M, int N, int K, int ldc)
{
    __shared__ float As[BK][BM + 4];
    __shared__ float Bs[BK][BN + 4];

    const int tid  = threadIdx.x;
    const int row0 = blockIdx.y * BM;
    const int col0 = blockIdx.x * BN;

    const int lr = tid >> 1;            // 0..127
    const int lc = (tid & 1) << 2;      // 0 or 4

    const int tx = tid & 15;
    const int ty = tid >> 4;

    float acc[8][8];
    #pragma unroll
    for (int i = 0; i < 8; i++)
        #pragma unroll
        for (int j = 0; j < 8; j++) acc[i][j] = 0.f;

    const float* Aptr = A + (size_t)(row0 + lr) * K + lc;
    const bool bvalid = (col0 + lr) < N;
    const float* Bptr = Bw + (size_t)(col0 + lr) * K + lc;

    for (int k0 = 0; k0 < K; k0 += BK) {
        float4 av = *(const float4*)(Aptr + k0);
        float4 bv = bvalid ? *(const float4*)(Bptr + k0) : make_float4(0.f, 0.f, 0.f, 0.f);
        As[lc + 0][lr] = av.x; As[lc + 1][lr] = av.y;
        As[lc + 2][lr] = av.z; As[lc + 3][lr] = av.w;
        Bs[lc + 0][lr] = bv.x; Bs[lc + 1][lr] = bv.y;
        Bs[lc + 2][lr] = bv.z; Bs[lc + 3][lr] = bv.w;
        __syncthreads();

        #pragma unroll
        for (int k = 0; k < BK; k++) {
            float4 a0 = *(const float4*)&As[k][ty * 4];
            float4 a1 = *(const float4*)&As[k][64 + ty * 4];
            float4 b0 = *(const float4*)&Bs[k][tx * 4];
            float4 b1 = *(const float4*)&Bs[k][64 + tx * 4];
            float a[8] = {a0.x, a0.y, a0.z, a0.w, a1.x, a1.y, a1.z, a1.w};
            float b[8] = {b0.x, b0.y, b0.z, b0.w, b1.x, b1.y, b1.z, b1.w};
            #pragma unroll
            for (int i = 0; i < 8; i++)
                #pragma unroll
                for (int j = 0; j < 8; j++)
                    acc[i][j] += a[i] * b[j];
        }
        __syncthreads();
    }

    #pragma unroll
    for (int ih = 0; ih < 2; ih++)
        #pragma unroll
        for (int i = 0; i < 4; i++) {
            int r = row0 + ih * 64 + ty * 4 + i;
            #pragma unroll
            for (int jh = 0; jh < 2; jh++)
                #pragma unroll
                for (int j = 0; j < 4; j++) {
                    int c = col0 + jh * 64 + tx * 4 + j;
                    if (c < N) {
                        float v = acc[ih * 4 + i][jh * 4 + j];
                        if (ADD) v += ADD[(size_t)r * ldc + c];
                        C[(size_t)r * ldc + c] = v;
                    }
                }
        }
}

// ---------------------------------------------------------------------------
// 6. Attention scores: S[bh][i][j] = (q_i . k_j) / 8 on 64x64 tiles,
//    lower triangle of tile grid only.
// ---------------------------------------------------------------------------
__global__ __launch_bounds__(256) void qk_kernel()
{
    int kj = blockIdx.x, qi = blockIdx.y, bh = blockIdx.z;
    if (kj > qi) return;
    int b = bh >> 4, h = bh & 15;

    __shared__ float Qs[64][68];   // [k][m], pre-scaled by 1/8
    __shared__ float Ks[64][68];   // [k][n]

    const float* qkv = d_ws + OFF_QKV;
    int tid = threadIdx.x;

    for (int e = tid; e < 64 * 64; e += 256) {
        int m = e >> 6, d = e & 63;
        Qs[d][m] = qkv[((size_t)(b * CAP_ + qi * 64 + m)) * (3 * D_) + h * 64 + d] * 0.125f;
        Ks[d][m] = qkv[((size_t)(b * CAP_ + kj * 64 + m)) * (3 * D_) + D_ + h * 64 + d];
    }
    __syncthreads();

    int tx = tid & 15, ty = tid >> 4;
    float acc[4][4];
    #pragma unroll
    for (int i = 0; i < 4; i++)
        #pragma unroll
        for (int j = 0; j < 4; j++) acc[i][j] = 0.f;

    #pragma unroll 4
    for (int k = 0; k < 64; k++) {
        float4 a = *(const float4*)&Qs[k][ty * 4];
        float4 bb = *(const float4*)&Ks[k][tx * 4];
        float av[4] = {a.x, a.y, a.z, a.w};
        float bv[4] = {bb.x, bb.y, bb.z, bb.w};
        #pragma unroll
        for (int i = 0; i < 4; i++)
            #pragma unroll
            for (int j = 0; j < 4; j++)
                acc[i][j] += av[i] * bv[j];
    }

    float* S = d_ws + OFF_S + (size_t)bh * CAP_ * CAP_;
    #pragma unroll
    for (int i = 0; i < 4; i++) {
        int r = qi * 64 + ty * 4 + i;
        #pragma unroll
        for (int j = 0; j < 4; j++)
            S[(size_t)r * CAP_ + kj * 64 + tx * 4 + j] = acc[i][j];
    }
}

// ---------------------------------------------------------------------------
// 7. Causal row softmax. Writes zeros for j > i so PV is a dense GEMM.
// ---------------------------------------------------------------------------
__global__ __launch_bounds__(128) void softmax_kernel()
{
    int i = blockIdx.x;
    int bh = blockIdx.y;
    float* row = d_ws + OFF_S + ((size_t)bh * CAP_ + i) * CAP_;
    int L = i + 1;
    int tid = threadIdx.x;

    __shared__ float red[4], red2[4];

    float mx = -1e30f;
    for (int j = tid; j < L; j += 128) mx = fmaxf(mx, row[j]);
    #pragma unroll
    for (int o = 16; o; o >>= 1) mx = fmaxf(mx, __shfl_xor_sync(0xFFFFFFFFu, mx, o));
    if ((tid & 31) == 0) red[tid >> 5] = mx;
    __syncthreads();
    mx = fmaxf(fmaxf(red[0], red[1]), fmaxf(red[2], red[3]));

    float sum = 0.f;
    for (int j = tid; j < L; j += 128) sum += __expf(row[j] - mx);
    #pragma unroll
    for (int o = 16; o; o >>= 1) sum += __shfl_xor_sync(0xFFFFFFFFu, sum, o);
    if ((tid & 31) == 0) red2[tid >> 5] = sum;
    __syncthreads();
    sum = red2[0] + red2[1] + red2[2] + red2[3];
    float inv = 1.f / sum;

    for (int j = tid; j < L; j += 128) row[j] = __expf(row[j] - mx) * inv;
    for (int j = L + tid; j < CAP_; j += 128) row[j] = 0.f;
}

// ---------------------------------------------------------------------------
// 8. PV: attn_out[b][i][h*64+d] = sum_j P[bh][i][j] * V[b][j][h][d]
//    Tiled 64x64, causal tile skip (zeros beyond row handled by softmax).
// ---------------------------------------------------------------------------
__global__ __launch_bounds__(256) void pv_kernel()
{
    int it = blockIdx.x;       // query tile 0..7
    int bh = blockIdx.y;
    int b = bh >> 4, h = bh & 15;
    int i0 = it * 64;
    int tid = threadIdx.x;

    __shared__ float Ps[64][68];   // [j][r]
    __shared__ float Vs[64][68];   // [j][d]

    const float* P = d_ws + OFF_S + (size_t)bh * CAP_ * CAP_;
    const float* qkv = d_ws + OFF_QKV;

    int tx = tid & 15, ty = tid >> 4;
    float acc[4][4];
    #pragma unroll
    for (int i = 0; i < 4; i++)
        #pragma unroll
        for (int j = 0; j < 4; j++) acc[i][j] = 0.f;

    for (int jt = 0; jt <= it; jt++) {
        for (int e = tid; e < 64 * 64; e += 256) {
            int r = e >> 6, c = e & 63;
            Ps[c][r] = P[(size_t)(i0 + r) * CAP_ + jt * 64 + c];
            Vs[r][c] = qkv[((size_t)(b * CAP_ + jt * 64 + r)) * (3 * D_) + 2 * D_ + h * 64 + c];
        }
        __syncthreads();
        #pragma unroll 4
        for (int j = 0; j < 64; j++) {
            float4 a = *(const float4*)&Ps[j][ty * 4];
            float4 bb = *(const float4*)&Vs[j][tx * 4];
            float av[4] = {a.x, a.y, a.z, a.w};
            float bv[4] = {bb.x, bb.y, bb.z, bb.w};
            #pragma unroll
            for (int ii = 0; ii < 4; ii++)
                #pragma unroll
                for (int jj = 0; jj < 4; jj++)
                    acc[ii][jj] += av[ii] * bv[jj];
        }
        __syncthreads();
    }

    float* O = d_ws + OFF_ATTN;
    #pragma unroll
    for (int ii = 0; ii < 4; ii++) {
        int r = b * CAP_ + i0 + ty * 4 + ii;
        #pragma unroll
        for (int jj = 0; jj < 4; jj++)
            O[(size_t)r * D_ + h * 64 + tx * 4 + jj] = acc[ii][jj];
    }
}

// ---------------------------------------------------------------------------
// 9. SwiGLU: u = silu(u1) * u2  (with zero padding in [DFF_, DFFP_))
// ---------------------------------------------------------------------------
__global__ __launch_bounds__(256) void swiglu_kernel()
{
    size_t e = (size_t)blockIdx.x * blockDim.x + threadIdx.x;
    if (e >= (size_t)M_ * DFFP_) return;
    int n = (int)(e % DFFP_);
    float val = 0.f;
    if (n < DFF_) {
        float a = d_ws[OFF_U1 + e];
        float c = d_ws[OFF_U2 + e];
        val = a / (1.f + __expf(-a)) * c;
    }
    d_ws[OFF_U + e] = val;
}

// ---------------------------------------------------------------------------
// 10. Repack W3 [D_, DFF_] -> [D_, DFFP_] zero-padded
// ---------------------------------------------------------------------------
__global__ __launch_bounds__(256) void repack_w3_kernel(const float* __restrict__ W3)
{
    size_t e = (size_t)blockIdx.x * blockDim.x + threadIdx.x;
    if (e >= (size_t)D_ * DFFP_) return;
    int n = (int)(e / DFFP_);
    int k = (int)(e - (size_t)n * DFFP_);
    d_ws[OFF_W3P + e] = (k < DFF_) ? W3[(size_t)n * DFF_ + k] : 0.f;
}

// ---------------------------------------------------------------------------
// 11. out = x (full copy), then scatter processed rows
// ---------------------------------------------------------------------------
__global__ __launch_bounds__(256) void copy_kernel(float* __restrict__ out,
                                                   const float* __restrict__ x)
{
    size_t i = (size_t)blockIdx.x * blockDim.x + threadIdx.x;
    if (i < (size_t)B_ * T_ * D_ / 4)
        ((float4*)out)[i] = ((const float4*)x)[i];
}

__global__ __launch_bounds__(256) void scatter_kernel(float* __restrict__ out)
{
    int row = blockIdx.x;
    int tid = threadIdx.x;
    int b = row >> 9;
    int t = d_idx[row];
    float4 v = ((const float4*)(d_ws + OFF_XPROC + (size_t)row * D_))[tid];
    ((float4*)(out + ((size_t)b * T_ + t) * D_))[tid] = v;
}

// ---------------------------------------------------------------------------
// Launcher
// ---------------------------------------------------------------------------
extern "C" void kernel_launch(void* const* d_in, const int* in_sizes, int n_in,
                              void* d_out, int out_size)
{
    const float* x    = (const float*)d_in[0];
    const float* wr   = (const float*)d_in[1];
    const float* Wqkv = (const float*)d_in[2];
    const float* Wout = (const float*)d_in[3];
    const float* g1   = (const float*)d_in[4];
    const float* g2   = (const float*)d_in[5];
    const float* W1   = (const float*)d_in[6];
    const float* W2   = (const float*)d_in[7];
    const float* W3   = (const float*)d_in[8];
    float* out = (float*)d_out;

    float* ws = nullptr;
    cudaGetSymbolAddress((void**)&ws, d_ws);

    // independent prep
    copy_kernel<<<(B_ * T_ * D_ / 4 + 255) / 256, 256>>>(out, x);
    repack_w3_kernel<<<(int)(((size_t)D_ * DFFP_ + 255) / 256), 256>>>(W3);

    // routing
    router_kernel<<<(B_ * T_ * 32 + 255) / 256, 256>>>(x, wr);
    topk_kernel<<<B_, 1024>>>();

    // gather + norm
    gather_rmsnorm_kernel<<<M_, 256>>>(x, g1);

    // QKV projection:  qkv = h @ Wqkv^T
    sgemm_nt<<<dim3(3 * D_ / BN, M_ / BM), 256>>>(ws + OFF_H, Wqkv, ws + OFF_QKV,
                                                  nullptr, M_, 3 * D_, D_, 3 * D_);

    // attention
    qk_kernel<<<dim3(8, 8, B_ * H_), 256>>>();
    softmax_kernel<<<dim3(CAP_, B_ * H_), 128>>>();
    pv_kernel<<<dim3(8, B_ * H_), 256>>>();

    // out projection with residual: y1 = x_sel + attn @ Wout^T
    sgemm_nt<<<dim3(D_ / BN, M_ / BM), 256>>>(ws + OFF_ATTN, Wout, ws + OFF_Y1,
                                              ws + OFF_XSEL, M_, D_, D_, D_);

    // second norm
    rmsnorm2_kernel<<<M_, 256>>>(g2);

    // FFN
    sgemm_nt<<<dim3((DFF_ + BN - 1) / BN, M_ / BM), 256>>>(ws + OFF_H2, W1, ws + OFF_U1,
                                                           nullptr, M_, DFF_, D_, DFFP_);
    sgemm_nt<<<dim3((DFF_ + BN - 1) / BN, M_ / BM), 256>>>(ws + OFF_H2, W2, ws + OFF_U2,
                                                           nullptr, M_, DFF_, D_, DFFP_);
    swiglu_kernel<<<(int)(((size_t)M_ * DFFP_ + 255) / 256), 256>>>();

    // x_proc = y1 + u @ W3p^T
    sgemm_nt<<<dim3(D_ / BN, M_ / BM), 256>>>(ws + OFF_U, ws + OFF_W3P, ws + OFF_XPROC,
                                              ws + OFF_Y1, M_, D_, DFFP_, D_);

    // scatter back
    scatter_kernel<<<M_, 256>>>(out);
}

// round 2
// speedup vs baseline: 2.3298x; 2.3298x over previous
#include <cuda_runtime.h>
#include <cstdint>

#define B_ 4
#define T_ 4096
#define D_ 1024
#define H_ 16
#define HD_ 64
#define CAP_ 512
#define M_ 2048            // B_ * CAP_
#define DFF_ 2730
#define DFFP_ 2736         // padded to multiple of 16 (GEMM BK) and 4 (float4)

// ---------------------------------------------------------------------------
// Workspace
// ---------------------------------------------------------------------------
constexpr size_t OFF_SCORES = 0;
constexpr size_t OFF_XSEL   = OFF_SCORES + (size_t)B_ * T_;
constexpr size_t OFF_H      = OFF_XSEL   + (size_t)M_ * D_;
constexpr size_t OFF_QKV    = OFF_H      + (size_t)M_ * D_;
constexpr size_t OFF_S      = OFF_QKV    + (size_t)M_ * 3 * D_;
constexpr size_t OFF_ATTN   = OFF_S      + (size_t)B_ * H_ * CAP_ * CAP_;
constexpr size_t OFF_Y1     = OFF_ATTN   + (size_t)M_ * D_;
constexpr size_t OFF_H2     = OFF_Y1     + (size_t)M_ * D_;
constexpr size_t OFF_U1     = OFF_H2     + (size_t)M_ * D_;
constexpr size_t OFF_U2     = OFF_U1     + (size_t)M_ * DFFP_;
constexpr size_t OFF_U      = OFF_U2     + (size_t)M_ * DFFP_;
constexpr size_t OFF_W3P    = OFF_U      + (size_t)M_ * DFFP_;
constexpr size_t OFF_XPROC  = OFF_W3P    + (size_t)D_ * DFFP_;
constexpr size_t OFF_WQKVR  = OFF_XPROC  + (size_t)M_ * D_;
constexpr size_t OFF_WOUTR  = OFF_WQKVR  + (size_t)3 * D_ * D_;
constexpr size_t OFF_W1R    = OFF_WOUTR  + (size_t)D_ * D_;
constexpr size_t OFF_W2R    = OFF_W1R    + (size_t)DFF_ * D_;
constexpr size_t WS_TOTAL   = OFF_W2R    + (size_t)DFF_ * D_;

__device__ __align__(256) float d_ws[WS_TOTAL];
__device__ int d_idx[M_];

// ---------------------------------------------------------------------------
// tf32 round-to-nearest helper
// ---------------------------------------------------------------------------
__device__ __forceinline__ float tf32r(float x) {
    uint32_t u;
    asm("cvt.rna.tf32.f32 %0, %1;" : "=r"(u) : "f"(x));
    return __uint_as_float(u);
}

// ---------------------------------------------------------------------------
// 1. Router
// ---------------------------------------------------------------------------
__global__ __launch_bounds__(256) void router_kernel(const float* __restrict__ x,
                                                     const float* __restrict__ wr)
{
    int warp = (blockIdx.x * blockDim.x + threadIdx.x) >> 5;
    int lane = threadIdx.x & 31;
    if (warp >= B_ * T_) return;
    const float4* xr  = (const float4*)(x + (size_t)warp * D_);
    const float4* wr4 = (const float4*)wr;
    float acc = 0.f;
    #pragma unroll
    for (int k = lane; k < D_ / 4; k += 32) {
        float4 a = xr[k], w = wr4[k];
        acc += a.x * w.x + a.y * w.y + a.z * w.z + a.w * w.w;
    }
    #pragma unroll
    for (int o = 16; o; o >>= 1) acc += __shfl_xor_sync(0xFFFFFFFFu, acc, o);
    if (lane == 0) d_ws[OFF_SCORES + warp] = acc;
}

// ---------------------------------------------------------------------------
// 2. Top-k bitonic sort
// ---------------------------------------------------------------------------
__global__ __launch_bounds__(1024) void topk_kernel()
{
    __shared__ unsigned long long key[T_];
    int b = blockIdx.x;
    for (int t = threadIdx.x; t < T_; t += 1024) {
        float s = d_ws[OFF_SCORES + (size_t)b * T_ + t];
        unsigned int u = __float_as_uint(s);
        u = (u & 0x80000000u) ? ~u : (u | 0x80000000u);
        key[t] = ((unsigned long long)u << 32) | (unsigned int)(0xFFFFFFFFu - (unsigned)t);
    }
    __syncthreads();
    for (int k = 2; k <= T_; k <<= 1) {
        for (int j = k >> 1; j > 0; j >>= 1) {
            for (int t = threadIdx.x; t < T_; t += 1024) {
                int l = t ^ j;
                if (l > t) {
                    unsigned long long a = key[t], c = key[l];
                    bool desc = ((t & k) == 0);
                    if (desc ? (a < c) : (a > c)) { key[t] = c; key[l] = a; }
                }
            }
            __syncthreads();
        }
    }
    for (int t = threadIdx.x; t < CAP_; t += 1024)
        d_idx[b * CAP_ + t] = (int)(0xFFFFFFFFu - (unsigned int)(key[t] & 0xFFFFFFFFu));
}

// ---------------------------------------------------------------------------
// Block reduce (256 threads)
// ---------------------------------------------------------------------------
__device__ __forceinline__ float block_reduce_sum_256(float v, float* red)
{
    #pragma unroll
    for (int o = 16; o; o >>= 1) v += __shfl_xor_sync(0xFFFFFFFFu, v, o);
    if ((threadIdx.x & 31) == 0) red[threadIdx.x >> 5] = v;
    __syncthreads();
    float tot = 0.f;
    #pragma unroll
    for (int w = 0; w < 8; w++) tot += red[w];
    return tot;
}

// ---------------------------------------------------------------------------
// 3. Gather + RMSNorm (h rounded to tf32 for the QKV GEMM)
// ---------------------------------------------------------------------------
__global__ __launch_bounds__(256) void gather_rmsnorm_kernel(const float* __restrict__ x,
                                                             const float* __restrict__ g)
{
    __shared__ float red[8];
    int row = blockIdx.x;
    int b = row >> 9;
    int t = d_idx[row];
    int tid = threadIdx.x;
    const float4* src = (const float4*)(x + ((size_t)b * T_ + t) * D_);
    float4 v = src[tid];
    float ss = v.x*v.x + v.y*v.y + v.z*v.z + v.w*v.w;
    float tot = block_reduce_sum_256(ss, red);
    float rinv = rsqrtf(tot * (1.f / D_) + 1e-6f);
    float4 gv = ((const float4*)g)[tid];
    ((float4*)(d_ws + OFF_XSEL + (size_t)row * D_))[tid] = v;
    float4 o;
    o.x = tf32r(v.x * rinv * gv.x); o.y = tf32r(v.y * rinv * gv.y);
    o.z = tf32r(v.z * rinv * gv.z); o.w = tf32r(v.w * rinv * gv.w);
    ((float4*)(d_ws + OFF_H + (size_t)row * D_))[tid] = o;
}

// ---------------------------------------------------------------------------
// 4. RMSNorm of y1 -> h2 (rounded)
// ---------------------------------------------------------------------------
__global__ __launch_bounds__(256) void rmsnorm2_kernel(const float* __restrict__ g)
{
    __shared__ float red[8];
    int row = blockIdx.x;
    int tid = threadIdx.x;
    float4 v = ((const float4*)(d_ws + OFF_Y1 + (size_t)row * D_))[tid];
    float ss = v.x*v.x + v.y*v.y + v.z*v.z + v.w*v.w;
    float tot = block_reduce_sum_256(ss, red);
    float rinv = rsqrtf(tot * (1.f / D_) + 1e-6f);
    float4 gv = ((const float4*)g)[tid];
    float4 o;
    o.x = tf32r(v.x * rinv * gv.x); o.y = tf32r(v.y * rinv * gv.y);
    o.z = tf32r(v.z * rinv * gv.z); o.w = tf32r(v.w * rinv * gv.w);
    ((float4*)(d_ws + OFF_H2 + (size_t)row * D_))[tid] = o;
}

// ---------------------------------------------------------------------------
// 5. TF32 tensor-core GEMM (NT): C[m][n] = sum_k A[m][k]*B[n][k] (+ ADD)
//    BM=BN=128, BK=16, 256 threads (8 warps as 2x4; warp tile 64x32).
//    A,B must be pre-rounded to tf32. M%128==0, K%16==0; N arbitrary (even).
// ---------------------------------------------------------------------------
#define GBM 128
#define GBN 128
#define GBK 16
#define GLD (GBK + 4)

__device__ __forceinline__ void cp_async16(uint32_t dst, const void* src, bool valid) {
    int sz = valid ? 16 : 0;
    asm volatile("cp.async.cg.shared.global [%0], [%1], 16, %2;\n"
                 :: "r"(dst), "l"(src), "r"(sz));
}

__device__ __forceinline__ void mma_tf32(float* c, const uint32_t* a, uint32_t b0, uint32_t b1) {
    asm volatile(
        "mma.sync.aligned.m16n8k8.row.col.f32.tf32.tf32.f32 "
        "{%0,%1,%2,%3}, {%4,%5,%6,%7}, {%8,%9}, {%0,%1,%2,%3};\n"
        : "+f"(c[0]), "+f"(c[1]), "+f"(c[2]), "+f"(c[3])
        : "r"(a[0]), "r"(a[1]), "r"(a[2]), "r"(a[3]), "r"(b0), "r"(b1));
}

__global__ __launch_bounds__(256) void tf32_gemm_nt(const float* __restrict__ A,
                                                    const float* __restrict__ Bw,
                                                    float* __restrict__ C,
                                                    const float* __restrict__ ADD,
                                                    int M, int N, int K, int ldc)
{
    __shared__ float As[2][GBM][GLD];
    __shared__ float Bs[2][GBN][GLD];

    const int tid  = threadIdx.x;
    const int lane = tid & 31, warp = tid >> 5;
    const int g    = lane >> 2, tg = lane & 3;
    const int wm   = warp >> 2;   // 0..1
    const int wn   = warp & 3;    // 0..3
    const int row0 = blockIdx.y * GBM;
    const int col0 = blockIdx.x * GBN;

    float acc[4][4][4];
    #pragma unroll
    for (int i = 0; i < 4; i++)
        #pragma unroll
        for (int j = 0; j < 4; j++)
            #pragma unroll
            for (int r = 0; r < 4; r++) acc[i][j][r] = 0.f;

    const int lr = tid >> 2;            // 0..63
    const int lk = (tid & 3) * 4;       // 0,4,8,12

    auto issue = [&](int buf, int k0) {
        #pragma unroll
        for (int i = 0; i < 2; i++) {
            int r = lr + 64 * i;
            uint32_t da = (uint32_t)__cvta_generic_to_shared(&As[buf][r][lk]);
            cp_async16(da, A + (size_t)(row0 + r) * K + k0 + lk, true);
            uint32_t db = (uint32_t)__cvta_generic_to_shared(&Bs[buf][r][lk]);
            cp_async16(db, Bw + (size_t)(col0 + r) * K + k0 + lk, (col0 + r) < N);
        }
        asm volatile("cp.async.commit_group;\n");
    };

    issue(0, 0);
    issue(1, GBK);

    int buf = 0;
    for (int k0 = 0; k0 < K; k0 += GBK) {
        if (k0 + GBK < K) asm volatile("cp.async.wait_group 1;\n");
        else              asm volatile("cp.async.wait_group 0;\n");
        __syncthreads();

        #pragma unroll
        for (int kk = 0; kk < GBK; kk += 8) {
            uint32_t af[4][4], bf[4][2];
            #pragma unroll
            for (int mt = 0; mt < 4; mt++) {
                const float* ap = &As[buf][wm * 64 + mt * 16 + g][kk + tg];
                af[mt][0] = __float_as_uint(ap[0]);
                af[mt][1] = __float_as_uint(ap[8 * GLD]);
                af[mt][2] = __float_as_uint(ap[4]);
                af[mt][3] = __float_as_uint(ap[8 * GLD + 4]);
            }
            #pragma unroll
            for (int nt = 0; nt < 4; nt++) {
                const float* bp = &Bs[buf][wn * 32 + nt * 8 + g][kk + tg];
                bf[nt][0] = __float_as_uint(bp[0]);
                bf[nt][1] = __float_as_uint(bp[4]);
            }
            #pragma unroll
            for (int mt = 0; mt < 4; mt++)
                #pragma unroll
                for (int nt = 0; nt < 4; nt++)
                    mma_tf32(acc[mt][nt], af[mt], bf[nt][0], bf[nt][1]);
        }
        __syncthreads();

        if (k0 + 2 * GBK < K) issue(buf, k0 + 2 * GBK);
        buf ^= 1;
    }

    // epilogue
    #pragma unroll
    for (int mt = 0; mt < 4; mt++) {
        int r1 = row0 + wm * 64 + mt * 16 + g;
        int r2 = r1 + 8;
        #pragma unroll
        for (int nt = 0; nt < 4; nt++) {
            int c = col0 + wn * 32 + nt * 8 + tg * 2;
            if (c < N) {
                float2 v0 = make_float2(acc[mt][nt][0], acc[mt][nt][1]);
                float2 v1 = make_float2(acc[mt][nt][2], acc[mt][nt][3]);
                if (ADD) {
                    float2 a0 = *(const float2*)&ADD[(size_t)r1 * ldc + c];
                    float2 a1 = *(const float2*)&ADD[(size_t)r2 * ldc + c];
                    v0.x += a0.x; v0.y += a0.y;
                    v1.x += a1.x; v1.y += a1.y;
                }
                *(float2*)&C[(size_t)r1 * ldc + c] = v0;
                *(float2*)&C[(size_t)r2 * ldc + c] = v1;
            }
        }
    }
}

// ---------------------------------------------------------------------------
// 6. Attention scores (fp32 SIMT), lower-triangle tiles only
// ---------------------------------------------------------------------------
__global__ __launch_bounds__(256) void qk_kernel()
{
    int kj = blockIdx.x, qi = blockIdx.y, bh = blockIdx.z;
    if (kj > qi) return;
    int b = bh >> 4, h = bh & 15;

    __shared__ float Qs[64][68];
    __shared__ float Ks[64][68];

    const float* qkv = d_ws + OFF_QKV;
    int tid = threadIdx.x;

    for (int e = tid; e < 64 * 64; e += 256) {
        int m = e >> 6, d = e & 63;
        Qs[d][m] = qkv[((size_t)(b * CAP_ + qi * 64 + m)) * (3 * D_) + h * 64 + d] * 0.125f;
        Ks[d][m] = qkv[((size_t)(b * CAP_ + kj * 64 + m)) * (3 * D_) + D_ + h * 64 + d];
    }
    __syncthreads();

    int tx = tid & 15, ty = tid >> 4;
    float acc[4][4];
    #pragma unroll
    for (int i = 0; i < 4; i++)
        #pragma unroll
        for (int j = 0; j < 4; j++) acc[i][j] = 0.f;

    #pragma unroll 4
    for (int k = 0; k < 64; k++) {
        float4 a = *(const float4*)&Qs[k][ty * 4];
        float4 bb = *(const float4*)&Ks[k][tx * 4];
        float av[4] = {a.x, a.y, a.z, a.w};
        float bv[4] = {bb.x, bb.y, bb.z, bb.w};
        #pragma unroll
        for (int i = 0; i < 4; i++)
            #pragma unroll
            for (int j = 0; j < 4; j++)
                acc[i][j] += av[i] * bv[j];
    }

    float* S = d_ws + OFF_S + (size_t)bh * CAP_ * CAP_;
    #pragma unroll
    for (int i = 0; i < 4; i++) {
        int r = qi * 64 + ty * 4 + i;
        #pragma unroll
        for (int j = 0; j < 4; j++)
            S[(size_t)r * CAP_ + kj * 64 + tx * 4 + j] = acc[i][j];
    }
}

// ---------------------------------------------------------------------------
// 7. Causal row softmax (zeros above diagonal)
// ---------------------------------------------------------------------------
__global__ __launch_bounds__(128) void softmax_kernel()
{
    int i = blockIdx.x;
    int bh = blockIdx.y;
    float* row = d_ws + OFF_S + ((size_t)bh * CAP_ + i) * CAP_;
    int L = i + 1;
    int tid = threadIdx.x;

    __shared__ float red[4], red2[4];

    float mx = -1e30f;
    for (int j = tid; j < L; j += 128) mx = fmaxf(mx, row[j]);
    #pragma unroll
    for (int o = 16; o; o >>= 1) mx = fmaxf(mx, __shfl_xor_sync(0xFFFFFFFFu, mx, o));
    if ((tid & 31) == 0) red[tid >> 5] = mx;
    __syncthreads();
    mx = fmaxf(fmaxf(red[0], red[1]), fmaxf(red[2], red[3]));

    float sum = 0.f;
    for (int j = tid; j < L; j += 128) sum += __expf(row[j] - mx);
    #pragma unroll
    for (int o = 16; o; o >>= 1) sum += __shfl_xor_sync(0xFFFFFFFFu, sum, o);
    if ((tid & 31) == 0) red2[tid >> 5] = sum;
    __syncthreads();
    sum = red2[0] + red2[1] + red2[2] + red2[3];
    float inv = 1.f / sum;

    for (int j = tid; j < L; j += 128) row[j] = __expf(row[j] - mx) * inv;
    for (int j = L + tid; j < CAP_; j += 128) row[j] = 0.f;
}

// ---------------------------------------------------------------------------
// 8. PV (fp32 SIMT) — output rounded to tf32 for the Wout GEMM
// ---------------------------------------------------------------------------
__global__ __launch_bounds__(256) void pv_kernel()
{
    int it = blockIdx.x;
    int bh = blockIdx.y;
    int b = bh >> 4, h = bh & 15;
    int i0 = it * 64;
    int tid = threadIdx.x;

    __shared__ float Ps[64][68];
    __shared__ float Vs[64][68];

    const float* P = d_ws + OFF_S + (size_t)bh * CAP_ * CAP_;
    const float* qkv = d_ws + OFF_QKV;

    int tx = tid & 15, ty = tid >> 4;
    float acc[4][4];
    #pragma unroll
    for (int i = 0; i < 4; i++)
        #pragma unroll
        for (int j = 0; j < 4; j++) acc[i][j] = 0.f;

    for (int jt = 0; jt <= it; jt++) {
        for (int e = tid; e < 64 * 64; e += 256) {
            int r = e >> 6, c = e & 63;
            Ps[c][r] = P[(size_t)(i0 + r) * CAP_ + jt * 64 + c];
            Vs[r][c] = qkv[((size_t)(b * CAP_ + jt * 64 + r)) * (3 * D_) + 2 * D_ + h * 64 + c];
        }
        __syncthreads();
        #pragma unroll 4
        for (int j = 0; j < 64; j++) {
            float4 a = *(const float4*)&Ps[j][ty * 4];
            float4 bb = *(const float4*)&Vs[j][tx * 4];
            float av[4] = {a.x, a.y, a.z, a.w};
            float bv[4] = {bb.x, bb.y, bb.z, bb.w};
            #pragma unroll
            for (int ii = 0; ii < 4; ii++)
                #pragma unroll
                for (int jj = 0; jj < 4; jj++)
                    acc[ii][jj] += av[ii] * bv[jj];
        }
        __syncthreads();
    }

    float* O = d_ws + OFF_ATTN;
    #pragma unroll
    for (int ii = 0; ii < 4; ii++) {
        int r = b * CAP_ + i0 + ty * 4 + ii;
        #pragma unroll
        for (int jj = 0; jj < 4; jj++)
            O[(size_t)r * D_ + h * 64 + tx * 4 + jj] = tf32r(acc[ii][jj]);
    }
}

// ---------------------------------------------------------------------------
// 9. SwiGLU (output rounded; padding zeroed)
// ---------------------------------------------------------------------------
__global__ __launch_bounds__(256) void swiglu_kernel()
{
    size_t e = (size_t)blockIdx.x * blockDim.x + threadIdx.x;
    if (e >= (size_t)M_ * DFFP_) return;
    int n = (int)(e % DFFP_);
    float val = 0.f;
    if (n < DFF_) {
        float a = d_ws[OFF_U1 + e];
        float c = d_ws[OFF_U2 + e];
        val = tf32r(a / (1.f + __expf(-a)) * c);
    }
    d_ws[OFF_U + e] = val;
}

// ---------------------------------------------------------------------------
// 10. Weight prep: padded+rounded W3, rounded copies of other weights
// ---------------------------------------------------------------------------
__global__ __launch_bounds__(256) void repack_w3_kernel(const float* __restrict__ W3)
{
    size_t e = (size_t)blockIdx.x * blockDim.x + threadIdx.x;
    if (e >= (size_t)D_ * DFFP_) return;
    int n = (int)(e / DFFP_);
    int k = (int)(e - (size_t)n * DFFP_);
    d_ws[OFF_W3P + e] = (k < DFF_) ? tf32r(W3[(size_t)n * DFF_ + k]) : 0.f;
}

__global__ __launch_bounds__(256) void round_copy_kernel(float* __restrict__ dst,
                                                         const float* __restrict__ src,
                                                         size_t n)
{
    size_t i = (size_t)blockIdx.x * blockDim.x + threadIdx.x;
    if (i < n) dst[i] = tf32r(src[i]);
}

// ---------------------------------------------------------------------------
// 11. copy + scatter
// ---------------------------------------------------------------------------
__global__ __launch_bounds__(256) void copy_kernel(float* __restrict__ out,
                                                   const float* __restrict__ x)
{
    size_t i = (size_t)blockIdx.x * blockDim.x + threadIdx.x;
    if (i < (size_t)B_ * T_ * D_ / 4)
        ((float4*)out)[i] = ((const float4*)x)[i];
}

__global__ __launch_bounds__(256) void scatter_kernel(float* __restrict__ out)
{
    int row = blockIdx.x;
    int tid = threadIdx.x;
    int b = row >> 9;
    int t = d_idx[row];
    float4 v = ((const float4*)(d_ws + OFF_XPROC + (size_t)row * D_))[tid];
    ((float4*)(out + ((size_t)b * T_ + t) * D_))[tid] = v;
}

// ---------------------------------------------------------------------------
// Launcher
// ---------------------------------------------------------------------------
extern "C" void kernel_launch(void* const* d_in, const int* in_sizes, int n_in,
                              void* d_out, int out_size)
{
    const float* x    = (const float*)d_in[0];
    const float* wr   = (const float*)d_in[1];
    const float* Wqkv = (const float*)d_in[2];
    const float* Wout = (const float*)d_in[3];
    const float* g1   = (const float*)d_in[4];
    const float* g2   = (const float*)d_in[5];
    const float* W1   = (const float*)d_in[6];
    const float* W2   = (const float*)d_in[7];
    const float* W3   = (const float*)d_in[8];
    float* out = (float*)d_out;

    float* ws = nullptr;
    cudaGetSymbolAddress((void**)&ws, d_ws);

    auto rc = [&](size_t off, const float* src, size_t n) {
        round_copy_kernel<<<(int)((n + 255) / 256), 256>>>(ws + off, src, n);
    };

    // independent prep
    copy_kernel<<<(B_ * T_ * D_ / 4 + 255) / 256, 256>>>(out, x);
    repack_w3_kernel<<<(int)(((size_t)D_ * DFFP_ + 255) / 256), 256>>>(W3);
    rc(OFF_WQKVR, Wqkv, (size_t)3 * D_ * D_);
    rc(OFF_WOUTR, Wout, (size_t)D_ * D_);
    rc(OFF_W1R,   W1,   (size_t)DFF_ * D_);
    rc(OFF_W2R,   W2,   (size_t)DFF_ * D_);

    // routing
    router_kernel<<<(B_ * T_ * 32 + 255) / 256, 256>>>(x, wr);
    topk_kernel<<<B_, 1024>>>();

    // gather + norm
    gather_rmsnorm_kernel<<<M_, 256>>>(x, g1);

    // QKV projection
    tf32_gemm_nt<<<dim3(3 * D_ / GBN, M_ / GBM), 256>>>(ws + OFF_H, ws + OFF_WQKVR,
                                                        ws + OFF_QKV, nullptr,
                                                        M_, 3 * D_, D_, 3 * D_);

    // attention
    qk_kernel<<<dim3(8, 8, B_ * H_), 256>>>();
    softmax_kernel<<<dim3(CAP_, B_ * H_), 128>>>();
    pv_kernel<<<dim3(8, B_ * H_), 256>>>();

    // out projection with residual
    tf32_gemm_nt<<<dim3(D_ / GBN, M_ / GBM), 256>>>(ws + OFF_ATTN, ws + OFF_WOUTR,
                                                    ws + OFF_Y1, ws + OFF_XSEL,
                                                    M_, D_, D_, D_);

    rmsnorm2_kernel<<<M_, 256>>>(g2);

    // FFN
    tf32_gemm_nt<<<dim3((DFF_ + GBN - 1) / GBN, M_ / GBM), 256>>>(ws + OFF_H2, ws + OFF_W1R,
                                                                  ws + OFF_U1, nullptr,
                                                                  M_, DFF_, D_, DFFP_);
    tf32_gemm_nt<<<dim3((DFF_ + GBN - 1) / GBN, M_ / GBM), 256>>>(ws + OFF_H2, ws + OFF_W2R,
                                                                  ws + OFF_U2, nullptr,
                                                                  M_, DFF_, D_, DFFP_);
    swiglu_kernel<<<(int)(((size_t)M_ * DFFP_ + 255) / 256), 256>>>();

    tf32_gemm_nt<<<dim3(D_ / GBN, M_ / GBM), 256>>>(ws + OFF_U, ws + OFF_W3P,
                                                    ws + OFF_XPROC, ws + OFF_Y1,
                                                    M_, D_, DFFP_, D_);

    scatter_kernel<<<M_, 256>>>(out);
}

// round 3
// speedup vs baseline: 2.9906x; 1.2836x over previous
#include <cuda_runtime.h>
#include <cstdint>
#include <cmath>

#define B_ 4
#define T_ 4096
#define D_ 1024
#define H_ 16
#define HD_ 64
#define CAP_ 512
#define M_ 2048
#define DFF_ 2730
#define DFFP_ 2736

// ---------------------------------------------------------------------------
// Workspace
// ---------------------------------------------------------------------------
constexpr size_t OFF_SCORES = 0;
constexpr size_t OFF_XSEL   = OFF_SCORES + (size_t)B_ * T_;
constexpr size_t OFF_H      = OFF_XSEL   + (size_t)M_ * D_;
constexpr size_t OFF_QKV    = OFF_H      + (size_t)M_ * D_;
constexpr size_t OFF_ATTN   = OFF_QKV    + (size_t)M_ * 3 * D_;
constexpr size_t OFF_Y1     = OFF_ATTN   + (size_t)M_ * D_;
constexpr size_t OFF_H2     = OFF_Y1     + (size_t)M_ * D_;
constexpr size_t OFF_U1     = OFF_H2     + (size_t)M_ * D_;
constexpr size_t OFF_U2     = OFF_U1     + (size_t)M_ * DFFP_;
constexpr size_t OFF_U      = OFF_U2     + (size_t)M_ * DFFP_;
constexpr size_t OFF_W3P    = OFF_U      + (size_t)M_ * DFFP_;
constexpr size_t OFF_XPROC  = OFF_W3P    + (size_t)D_ * DFFP_;
constexpr size_t OFF_WQKVR  = OFF_XPROC  + (size_t)M_ * D_;
constexpr size_t OFF_WOUTR  = OFF_WQKVR  + (size_t)3 * D_ * D_;
constexpr size_t OFF_W1R    = OFF_WOUTR  + (size_t)D_ * D_;
constexpr size_t OFF_W2R    = OFF_W1R    + (size_t)DFF_ * D_;
constexpr size_t WS_TOTAL   = OFF_W2R    + (size_t)DFF_ * D_;

__device__ __align__(256) float d_ws[WS_TOTAL];
__device__ int d_idx[M_];
__device__ unsigned long long d_keys[B_ * T_];

// ---------------------------------------------------------------------------
__device__ __forceinline__ float tf32r(float x) {
    uint32_t u;
    asm("cvt.rna.tf32.f32 %0, %1;" : "=r"(u) : "f"(x));
    return __uint_as_float(u);
}

// ---------------------------------------------------------------------------
// 1. Router
// ---------------------------------------------------------------------------
__global__ __launch_bounds__(256) void router_kernel(const float* __restrict__ x,
                                                     const float* __restrict__ wr)
{
    int warp = (blockIdx.x * blockDim.x + threadIdx.x) >> 5;
    int lane = threadIdx.x & 31;
    if (warp >= B_ * T_) return;
    const float4* xr  = (const float4*)(x + (size_t)warp * D_);
    const float4* wr4 = (const float4*)wr;
    float acc = 0.f;
    #pragma unroll
    for (int k = lane; k < D_ / 4; k += 32) {
        float4 a = xr[k], w = wr4[k];
        acc += a.x * w.x + a.y * w.y + a.z * w.z + a.w * w.w;
    }
    #pragma unroll
    for (int o = 16; o; o >>= 1) acc += __shfl_xor_sync(0xFFFFFFFFu, acc, o);
    if (lane == 0) d_ws[OFF_SCORES + warp] = acc;
}

// ---------------------------------------------------------------------------
// 2a. Top-k phase 1: sort 512-element chunks descending (32 blocks)
// ---------------------------------------------------------------------------
__global__ __launch_bounds__(256) void topk_sort512_kernel()
{
    __shared__ unsigned long long key[512];
    int chunk = blockIdx.x;
    int b = chunk >> 3;
    int c0 = (chunk & 7) * 512;

    for (int t = threadIdx.x; t < 512; t += 256) {
        int gi = c0 + t;
        float s = d_ws[OFF_SCORES + (size_t)b * T_ + gi];
        unsigned int u = __float_as_uint(s);
        u = (u & 0x80000000u) ? ~u : (u | 0x80000000u);
        key[t] = ((unsigned long long)u << 32) | (unsigned int)(0xFFFFFFFFu - (unsigned)gi);
    }
    __syncthreads();
    for (int k = 2; k <= 512; k <<= 1) {
        for (int j = k >> 1; j > 0; j >>= 1) {
            for (int t = threadIdx.x; t < 512; t += 256) {
                int l = t ^ j;
                if (l > t) {
                    unsigned long long a = key[t], c = key[l];
                    bool desc = ((t & k) == 0);
                    if (desc ? (a < c) : (a > c)) { key[t] = c; key[l] = a; }
                }
            }
            __syncthreads();
        }
    }
    for (int t = threadIdx.x; t < 512; t += 256)
        d_keys[(size_t)b * T_ + c0 + t] = key[t];
}

// ---------------------------------------------------------------------------
// 2b. Top-k phase 2: merge 8 sorted-512 lists keeping top-512 (4 blocks)
//     max(desc, reversed-desc) is bitonic -> one bitonic merge re-sorts.
// ---------------------------------------------------------------------------
__global__ __launch_bounds__(512) void topk_merge_kernel()
{
    __shared__ unsigned long long key[T_];
    int b = blockIdx.x;
    for (int t = threadIdx.x; t < T_; t += 512)
        key[t] = d_keys[(size_t)b * T_ + t];
    __syncthreads();

    #pragma unroll
    for (int r = 0; r < 3; r++) {
        int pairs = 4 >> r;
        int stride = 1024 << r;
        int half = 512 << r;
        // elementwise max into A
        for (int e = threadIdx.x; e < pairs * 512; e += 512) {
            int p = e >> 9, i = e & 511;
            int base = p * stride;
            unsigned long long a = key[base + i];
            unsigned long long bb = key[base + half + 511 - i];
            if (bb > a) key[base + i] = bb;
        }
        __syncthreads();
        // bitonic merge (descending) each surviving 512-list
        for (int j = 256; j > 0; j >>= 1) {
            for (int e = threadIdx.x; e < pairs * 256; e += 512) {
                int p = e >> 8, q = e & 255;
                int i = ((q & ~(j - 1)) << 1) | (q & (j - 1));
                int base = p * stride;
                unsigned long long a = key[base + i], c = key[base + i + j];
                if (a < c) { key[base + i] = c; key[base + i + j] = a; }
            }
            __syncthreads();
        }
    }
    for (int t = threadIdx.x; t < CAP_; t += 512)
        d_idx[b * CAP_ + t] = (int)(0xFFFFFFFFu - (unsigned int)(key[t] & 0xFFFFFFFFu));
}

// ---------------------------------------------------------------------------
__device__ __forceinline__ float block_reduce_sum_256(float v, float* red)
{
    #pragma unroll
    for (int o = 16; o; o >>= 1) v += __shfl_xor_sync(0xFFFFFFFFu, v, o);
    if ((threadIdx.x & 31) == 0) red[threadIdx.x >> 5] = v;
    __syncthreads();
    float tot = 0.f;
    #pragma unroll
    for (int w = 0; w < 8; w++) tot += red[w];
    return tot;
}

// ---------------------------------------------------------------------------
// 3. Gather + RMSNorm
// ---------------------------------------------------------------------------
__global__ __launch_bounds__(256) void gather_rmsnorm_kernel(const float* __restrict__ x,
                                                             const float* __restrict__ g)
{
    __shared__ float red[8];
    int row = blockIdx.x;
    int b = row >> 9;
    int t = d_idx[row];
    int tid = threadIdx.x;
    float4 v = ((const float4*)(x + ((size_t)b * T_ + t) * D_))[tid];
    float ss = v.x*v.x + v.y*v.y + v.z*v.z + v.w*v.w;
    float tot = block_reduce_sum_256(ss, red);
    float rinv = rsqrtf(tot * (1.f / D_) + 1e-6f);
    float4 gv = ((const float4*)g)[tid];
    ((float4*)(d_ws + OFF_XSEL + (size_t)row * D_))[tid] = v;
    float4 o;
    o.x = tf32r(v.x * rinv * gv.x); o.y = tf32r(v.y * rinv * gv.y);
    o.z = tf32r(v.z * rinv * gv.z); o.w = tf32r(v.w * rinv * gv.w);
    ((float4*)(d_ws + OFF_H + (size_t)row * D_))[tid] = o;
}

// ---------------------------------------------------------------------------
// 4. RMSNorm y1 -> h2
// ---------------------------------------------------------------------------
__global__ __launch_bounds__(256) void rmsnorm2_kernel(const float* __restrict__ g)
{
    __shared__ float red[8];
    int row = blockIdx.x;
    int tid = threadIdx.x;
    float4 v = ((const float4*)(d_ws + OFF_Y1 + (size_t)row * D_))[tid];
    float ss = v.x*v.x + v.y*v.y + v.z*v.z + v.w*v.w;
    float tot = block_reduce_sum_256(ss, red);
    float rinv = rsqrtf(tot * (1.f / D_) + 1e-6f);
    float4 gv = ((const float4*)g)[tid];
    float4 o;
    o.x = tf32r(v.x * rinv * gv.x); o.y = tf32r(v.y * rinv * gv.y);
    o.z = tf32r(v.z * rinv * gv.z); o.w = tf32r(v.w * rinv * gv.w);
    ((float4*)(d_ws + OFF_H2 + (size_t)row * D_))[tid] = o;
}

// ---------------------------------------------------------------------------
// 5. TF32 GEMM (NT) — validated fragment layout from round 2.
// ---------------------------------------------------------------------------
#define GBM 128
#define GBN 128
#define GBK 16
#define GLD (GBK + 4)

__device__ __forceinline__ void cp_async16(uint32_t dst, const void* src, bool valid) {
    int sz = valid ? 16 : 0;
    asm volatile("cp.async.cg.shared.global [%0], [%1], 16, %2;\n"
                 :: "r"(dst), "l"(src), "r"(sz));
}

__device__ __forceinline__ void mma_tf32(float* c, const uint32_t* a, uint32_t b0, uint32_t b1) {
    asm volatile(
        "mma.sync.aligned.m16n8k8.row.col.f32.tf32.tf32.f32 "
        "{%0,%1,%2,%3}, {%4,%5,%6,%7}, {%8,%9}, {%0,%1,%2,%3};\n"
        : "+f"(c[0]), "+f"(c[1]), "+f"(c[2]), "+f"(c[3])
        : "r"(a[0]), "r"(a[1]), "r"(a[2]), "r"(a[3]), "r"(b0), "r"(b1));
}

__global__ __launch_bounds__(256) void tf32_gemm_nt(const float* __restrict__ A,
                                                    const float* __restrict__ Bw,
                                                    float* __restrict__ C,
                                                    const float* __restrict__ ADD,
                                                    int M, int N, int K, int ldc,
                                                    int roundC)
{
    __shared__ float As[2][GBM][GLD];
    __shared__ float Bs[2][GBN][GLD];

    const int tid  = threadIdx.x;
    const int lane = tid & 31, warp = tid >> 5;
    const int g    = lane >> 2, tg = lane & 3;
    const int wm   = warp >> 2;
    const int wn   = warp & 3;
    const int row0 = blockIdx.y * GBM;
    const int col0 = blockIdx.x * GBN;

    float acc[4][4][4];
    #pragma unroll
    for (int i = 0; i < 4; i++)
        #pragma unroll
        for (int j = 0; j < 4; j++)
            #pragma unroll
            for (int r = 0; r < 4; r++) acc[i][j][r] = 0.f;

    const int lr = tid >> 2;
    const int lk = (tid & 3) * 4;

    auto issue = [&](int buf, int k0) {
        #pragma unroll
        for (int i = 0; i < 2; i++) {
            int r = lr + 64 * i;
            uint32_t da = (uint32_t)__cvta_generic_to_shared(&As[buf][r][lk]);
            cp_async16(da, A + (size_t)(row0 + r) * K + k0 + lk, true);
            uint32_t db = (uint32_t)__cvta_generic_to_shared(&Bs[buf][r][lk]);
            cp_async16(db, Bw + (size_t)(col0 + r) * K + k0 + lk, (col0 + r) < N);
        }
        asm volatile("cp.async.commit_group;\n");
    };

    issue(0, 0);
    issue(1, GBK);

    int buf = 0;
    for (int k0 = 0; k0 < K; k0 += GBK) {
        if (k0 + GBK < K) asm volatile("cp.async.wait_group 1;\n");
        else              asm volatile("cp.async.wait_group 0;\n");
        __syncthreads();

        #pragma unroll
        for (int kk = 0; kk < GBK; kk += 8) {
            uint32_t af[4][4], bf[4][2];
            #pragma unroll
            for (int mt = 0; mt < 4; mt++) {
                const float* ap = &As[buf][wm * 64 + mt * 16 + g][kk + tg];
                af[mt][0] = __float_as_uint(ap[0]);
                af[mt][1] = __float_as_uint(ap[8 * GLD]);
                af[mt][2] = __float_as_uint(ap[4]);
                af[mt][3] = __float_as_uint(ap[8 * GLD + 4]);
            }
            #pragma unroll
            for (int nt = 0; nt < 4; nt++) {
                const float* bp = &Bs[buf][wn * 32 + nt * 8 + g][kk + tg];
                bf[nt][0] = __float_as_uint(bp[0]);
                bf[nt][1] = __float_as_uint(bp[4]);
            }
            #pragma unroll
            for (int mt = 0; mt < 4; mt++)
                #pragma unroll
                for (int nt = 0; nt < 4; nt++)
                    mma_tf32(acc[mt][nt], af[mt], bf[nt][0], bf[nt][1]);
        }
        __syncthreads();

        if (k0 + 2 * GBK < K) issue(buf, k0 + 2 * GBK);
        buf ^= 1;
    }

    #pragma unroll
    for (int mt = 0; mt < 4; mt++) {
        int r1 = row0 + wm * 64 + mt * 16 + g;
        int r2 = r1 + 8;
        #pragma unroll
        for (int nt = 0; nt < 4; nt++) {
            int c = col0 + wn * 32 + nt * 8 + tg * 2;
            if (c < N) {
                float2 v0 = make_float2(acc[mt][nt][0], acc[mt][nt][1]);
                float2 v1 = make_float2(acc[mt][nt][2], acc[mt][nt][3]);
                if (ADD) {
                    float2 a0 = *(const float2*)&ADD[(size_t)r1 * ldc + c];
                    float2 a1 = *(const float2*)&ADD[(size_t)r2 * ldc + c];
                    v0.x += a0.x; v0.y += a0.y;
                    v1.x += a1.x; v1.y += a1.y;
                }
                if (roundC) {
                    v0.x = tf32r(v0.x); v0.y = tf32r(v0.y);
                    v1.x = tf32r(v1.x); v1.y = tf32r(v1.y);
                }
                *(float2*)&C[(size_t)r1 * ldc + c] = v0;
                *(float2*)&C[(size_t)r2 * ldc + c] = v1;
            }
        }
    }
}

// ---------------------------------------------------------------------------
// 6. Fused flash attention (TF32 mma, online softmax).
//    One block per (bh, q-tile of 64). 128 threads = 4 warps; warp owns 16 rows.
//    smem: Qs[64][68], Ks[64][68], Ps[64][68], Vs[64][72], stats 3*64.
// ---------------------------------------------------------------------------
#define FA_PQ 68
#define FA_PV 72
constexpr int FA_SMEM_FLOATS = 64 * FA_PQ * 3 + 64 * FA_PV + 3 * 64;
constexpr int FA_SMEM_BYTES  = FA_SMEM_FLOATS * 4;

__global__ __launch_bounds__(128) void flash_attn_kernel()
{
    extern __shared__ float fsm[];
    float* Qs   = fsm;
    float* Ks   = Qs + 64 * FA_PQ;
    float* Ps   = Ks + 64 * FA_PQ;
    float* Vs   = Ps + 64 * FA_PQ;          // natural layout [j][d], pitch 72
    float* smM  = Vs + 64 * FA_PV;
    float* smL  = smM + 64;
    float* smSc = smL + 64;

    const int bh = blockIdx.x;
    const int it = 7 - blockIdx.y;          // heavy tiles first
    const int b  = bh >> 4, h = bh & 15;
    const int tid = threadIdx.x;
    const int lane = tid & 31, w = tid >> 5;
    const int g = lane >> 2, tg = lane & 3;
    const int m0 = w * 16;

    const float* qkv = d_ws + OFF_QKV;
    const int tokQ0 = b * CAP_ + it * 64;

    // load Q tile (rounded tf32 already, from QKV GEMM epilogue)
    #pragma unroll
    for (int i = 0; i < 8; i++) {
        int f = tid + 128 * i;              // float4 index, 1024 total
        int r = f >> 4, c4 = f & 15;
        uint32_t dst = (uint32_t)__cvta_generic_to_shared(&Qs[r * FA_PQ + c4 * 4]);
        cp_async16(dst, qkv + (size_t)(tokQ0 + r) * (3 * D_) + h * 64 + c4 * 4, true);
    }
    asm volatile("cp.async.commit_group;\n");

    if (tid < 64) { smM[tid] = -1e30f; smL[tid] = 0.f; }

    float acc[8][4];
    #pragma unroll
    for (int nt = 0; nt < 8; nt++)
        #pragma unroll
        for (int r = 0; r < 4; r++) acc[nt][r] = 0.f;

    for (int jt = 0; jt <= it; jt++) {
        // load K, V tiles
        const int tokK0 = b * CAP_ + jt * 64;
        #pragma unroll
        for (int i = 0; i < 8; i++) {
            int f = tid + 128 * i;
            int r = f >> 4, c4 = f & 15;
            uint32_t dk = (uint32_t)__cvta_generic_to_shared(&Ks[r * FA_PQ + c4 * 4]);
            cp_async16(dk, qkv + (size_t)(tokK0 + r) * (3 * D_) + D_ + h * 64 + c4 * 4, true);
            uint32_t dv = (uint32_t)__cvta_generic_to_shared(&Vs[r * FA_PV + c4 * 4]);
            cp_async16(dv, qkv + (size_t)(tokK0 + r) * (3 * D_) + 2 * D_ + h * 64 + c4 * 4, true);
        }
        asm volatile("cp.async.commit_group;\n");
        asm volatile("cp.async.wait_group 0;\n");
        __syncthreads();

        // ---- S = Q K^T (warp rows m0..m0+15, all 64 cols) ----
        float sacc[8][4];
        #pragma unroll
        for (int nt = 0; nt < 8; nt++)
            #pragma unroll
            for (int r = 0; r < 4; r++) sacc[nt][r] = 0.f;

        #pragma unroll
        for (int kk = 0; kk < 64; kk += 8) {
            uint32_t a[4];
            const float* ap = &Qs[(m0 + g) * FA_PQ + kk + tg];
            a[0] = __float_as_uint(ap[0]);
            a[1] = __float_as_uint(ap[8 * FA_PQ]);
            a[2] = __float_as_uint(ap[4]);
            a[3] = __float_as_uint(ap[8 * FA_PQ + 4]);
            #pragma unroll
            for (int nt = 0; nt < 8; nt++) {
                const float* bp = &Ks[(nt * 8 + g) * FA_PQ + kk + tg];
                mma_tf32(sacc[nt], a, __float_as_uint(bp[0]), __float_as_uint(bp[4]));
            }
        }

        // write S tile (scaled, causally masked on diagonal tile)
        const bool diag = (jt == it);
        const int r0l = m0 + g, r1l = r0l + 8;
        #pragma unroll
        for (int nt = 0; nt < 8; nt++) {
            int c0 = nt * 8 + 2 * tg, c1 = c0 + 1;
            float s00 = sacc[nt][0] * 0.125f, s01 = sacc[nt][1] * 0.125f;
            float s10 = sacc[nt][2] * 0.125f, s11 = sacc[nt][3] * 0.125f;
            if (diag) {
                if (c0 > r0l) s00 = -1e30f;
                if (c1 > r0l) s01 = -1e30f;
                if (c0 > r1l) s10 = -1e30f;
                if (c1 > r1l) s11 = -1e30f;
            }
            Ps[r0l * FA_PQ + c0] = s00; Ps[r0l * FA_PQ + c1] = s01;
            Ps[r1l * FA_PQ + c0] = s10; Ps[r1l * FA_PQ + c1] = s11;
        }
        __syncwarp();

        // ---- online softmax on warp's 16 rows ----
        {
            int row = m0 + (lane >> 1);
            int cbase = (lane & 1) * 32;
            float* prow = &Ps[row * FA_PQ + cbase];
            float mloc = -1e30f;
            #pragma unroll
            for (int c = 0; c < 32; c++) mloc = fmaxf(mloc, prow[c]);
            mloc = fmaxf(mloc, __shfl_xor_sync(0xFFFFFFFFu, mloc, 1));
            float mOld = smM[row];
            float mNew = fmaxf(mOld, mloc);
            float sc = __expf(mOld - mNew);
            float s = 0.f;
            #pragma unroll
            for (int c = 0; c < 32; c++) {
                float e = __expf(prow[c] - mNew);
                prow[c] = tf32r(e);
                s += e;
            }
            s += __shfl_xor_sync(0xFFFFFFFFu, s, 1);
            if ((lane & 1) == 0) {
                smM[row]  = mNew;
                smL[row]  = smL[row] * sc + s;
                smSc[row] = sc;
            }
        }
        __syncwarp();

        // ---- rescale O acc, then O += P V ----
        {
            float sc0 = smSc[m0 + g], sc1 = smSc[m0 + g + 8];
            #pragma unroll
            for (int nt = 0; nt < 8; nt++) {
                acc[nt][0] *= sc0; acc[nt][1] *= sc0;
                acc[nt][2] *= sc1; acc[nt][3] *= sc1;
            }
        }
        #pragma unroll
        for (int kk = 0; kk < 64; kk += 8) {
            uint32_t a[4];
            const float* ap = &Ps[(m0 + g) * FA_PQ + kk + tg];
            a[0] = __float_as_uint(ap[0]);
            a[1] = __float_as_uint(ap[8 * FA_PQ]);
            a[2] = __float_as_uint(ap[4]);
            a[3] = __float_as_uint(ap[8 * FA_PQ + 4]);
            #pragma unroll
            for (int nt = 0; nt < 8; nt++) {
                // B[n][k] = V^T[d][j] = Vs[j][d]
                uint32_t b0 = __float_as_uint(Vs[(kk + tg) * FA_PV + nt * 8 + g]);
                uint32_t b1 = __float_as_uint(Vs[(kk + tg + 4) * FA_PV + nt * 8 + g]);
                mma_tf32(acc[nt], a, b0, b1);
            }
        }
        __syncthreads();   // protect Ks/Vs before next jt overwrites
    }

    // ---- finalize: O / l, round to tf32, store ----
    float inv0 = 1.f / smL[m0 + g];
    float inv1 = 1.f / smL[m0 + g + 8];
    float* O = d_ws + OFF_ATTN;
    int tok0 = tokQ0 + m0 + g;
    #pragma unroll
    for (int nt = 0; nt < 8; nt++) {
        int c = h * 64 + nt * 8 + 2 * tg;
        float2 v0 = make_float2(tf32r(acc[nt][0] * inv0), tf32r(acc[nt][1] * inv0));
        float2 v1 = make_float2(tf32r(acc[nt][2] * inv1), tf32r(acc[nt][3] * inv1));
        *(float2*)&O[(size_t)tok0 * D_ + c] = v0;
        *(float2*)&O[(size_t)(tok0 + 8) * D_ + c] = v1;
    }
}

// ---------------------------------------------------------------------------
// 7. SwiGLU
// ---------------------------------------------------------------------------
__global__ __launch_bounds__(256) void swiglu_kernel()
{
    size_t e = (size_t)blockIdx.x * blockDim.x + threadIdx.x;
    if (e >= (size_t)M_ * DFFP_) return;
    int n = (int)(e % DFFP_);
    float val = 0.f;
    if (n < DFF_) {
        float a = d_ws[OFF_U1 + e];
        float c = d_ws[OFF_U2 + e];
        val = tf32r(a / (1.f + __expf(-a)) * c);
    }
    d_ws[OFF_U + e] = val;
}

// ---------------------------------------------------------------------------
// 8. Weight prep
// ---------------------------------------------------------------------------
__global__ __launch_bounds__(256) void repack_w3_kernel(const float* __restrict__ W3)
{
    size_t e = (size_t)blockIdx.x * blockDim.x + threadIdx.x;
    if (e >= (size_t)D_ * DFFP_) return;
    int n = (int)(e / DFFP_);
    int k = (int)(e - (size_t)n * DFFP_);
    d_ws[OFF_W3P + e] = (k < DFF_) ? tf32r(W3[(size_t)n * DFF_ + k]) : 0.f;
}

__global__ __launch_bounds__(256) void round_copy_kernel(float* __restrict__ dst,
                                                         const float* __restrict__ src,
                                                         size_t n)
{
    size_t i = (size_t)blockIdx.x * blockDim.x + threadIdx.x;
    if (i < n) dst[i] = tf32r(src[i]);
}

// ---------------------------------------------------------------------------
// 9. copy + scatter
// ---------------------------------------------------------------------------
__global__ __launch_bounds__(256) void copy_kernel(float* __restrict__ out,
                                                   const float* __restrict__ x)
{
    size_t i = (size_t)blockIdx.x * blockDim.x + threadIdx.x;
    if (i < (size_t)B_ * T_ * D_ / 4)
        ((float4*)out)[i] = ((const float4*)x)[i];
}

__global__ __launch_bounds__(256) void scatter_kernel(float* __restrict__ out)
{
    int row = blockIdx.x;
    int tid = threadIdx.x;
    int b = row >> 9;
    int t = d_idx[row];
    float4 v = ((const float4*)(d_ws + OFF_XPROC + (size_t)row * D_))[tid];
    ((float4*)(out + ((size_t)b * T_ + t) * D_))[tid] = v;
}

// ---------------------------------------------------------------------------
// Launcher
// ---------------------------------------------------------------------------
extern "C" void kernel_launch(void* const* d_in, const int* in_sizes, int n_in,
                              void* d_out, int out_size)
{
    const float* x    = (const float*)d_in[0];
    const float* wr   = (const float*)d_in[1];
    const float* Wqkv = (const float*)d_in[2];
    const float* Wout = (const float*)d_in[3];
    const float* g1   = (const float*)d_in[4];
    const float* g2   = (const float*)d_in[5];
    const float* W1   = (const float*)d_in[6];
    const float* W2   = (const float*)d_in[7];
    const float* W3   = (const float*)d_in[8];
    float* out = (float*)d_out;

    float* ws = nullptr;
    cudaGetSymbolAddress((void**)&ws, d_ws);
    cudaFuncSetAttribute(flash_attn_kernel,
                         cudaFuncAttributeMaxDynamicSharedMemorySize, FA_SMEM_BYTES);

    auto rc = [&](size_t off, const float* src, size_t n) {
        round_copy_kernel<<<(int)((n + 255) / 256), 256>>>(ws + off, src, n);
    };

    copy_kernel<<<(B_ * T_ * D_ / 4 + 255) / 256, 256>>>(out, x);
    repack_w3_kernel<<<(int)(((size_t)D_ * DFFP_ + 255) / 256), 256>>>(W3);
    rc(OFF_WQKVR, Wqkv, (size_t)3 * D_ * D_);
    rc(OFF_WOUTR, Wout, (size_t)D_ * D_);
    rc(OFF_W1R,   W1,   (size_t)DFF_ * D_);
    rc(OFF_W2R,   W2,   (size_t)DFF_ * D_);

    router_kernel<<<(B_ * T_ * 32 + 255) / 256, 256>>>(x, wr);
    topk_sort512_kernel<<<32, 256>>>();
    topk_merge_kernel<<<B_, 512>>>();

    gather_rmsnorm_kernel<<<M_, 256>>>(x, g1);

    // QKV projection, output rounded to tf32 (feeds attention mmas)
    tf32_gemm_nt<<<dim3(3 * D_ / GBN, M_ / GBM), 256>>>(ws + OFF_H, ws + OFF_WQKVR,
                                                        ws + OFF_QKV, nullptr,
                                                        M_, 3 * D_, D_, 3 * D_, 1);

    flash_attn_kernel<<<dim3(B_ * H_, 8), 128, FA_SMEM_BYTES>>>();

    tf32_gemm_nt<<<dim3(D_ / GBN, M_ / GBM), 256>>>(ws + OFF_ATTN, ws + OFF_WOUTR,
                                                    ws + OFF_Y1, ws + OFF_XSEL,
                                                    M_, D_, D_, D_, 0);

    rmsnorm2_kernel<<<M_, 256>>>(g2);

    tf32_gemm_nt<<<dim3((DFF_ + GBN - 1) / GBN, M_ / GBM), 256>>>(ws + OFF_H2, ws + OFF_W1R,
                                                                  ws + OFF_U1, nullptr,
                                                                  M_, DFF_, D_, DFFP_, 0);
    tf32_gemm_nt<<<dim3((DFF_ + GBN - 1) / GBN, M_ / GBM), 256>>>(ws + OFF_H2, ws + OFF_W2R,
                                                                  ws + OFF_U2, nullptr,
                                                                  M_, DFF_, D_, DFFP_, 0);
    swiglu_kernel<<<(int)(((size_t)M_ * DFFP_ + 255) / 256), 256>>>();

    tf32_gemm_nt<<<dim3(D_ / GBN, M_ / GBM), 256>>>(ws + OFF_U, ws + OFF_W3P,
                                                    ws + OFF_XPROC, ws + OFF_Y1,
                                                    M_, D_, DFFP_, D_, 0);

    scatter_kernel<<<M_, 256>>>(out);
}

// round 4
// speedup vs baseline: 4.7972x; 1.6041x over previous
#include <cuda_runtime.h>
#include <cuda_bf16.h>
#include <cstdint>
#include <cmath>

#define B_ 4
#define T_ 4096
#define D_ 1024
#define H_ 16
#define HD_ 64
#define CAP_ 512
#define M_ 2048
#define DFF_ 2730
#define DFFP2_ 2752        // padded to multiple of 32 (bf16 GEMM BK)

// ---------------------------------------------------------------------------
// fp32 workspace
// ---------------------------------------------------------------------------
constexpr size_t OFF_SCORES = 0;
constexpr size_t OFF_XSEL   = OFF_SCORES + (size_t)B_ * T_;
constexpr size_t OFF_Y1     = OFF_XSEL   + (size_t)M_ * D_;
constexpr size_t OFF_XPROC  = OFF_Y1     + (size_t)M_ * D_;
constexpr size_t WS_TOTAL   = OFF_XPROC  + (size_t)M_ * D_;

__device__ __align__(256) float d_ws[WS_TOTAL];

// bf16 workspace (element offsets)
constexpr size_t HB_H    = 0;
constexpr size_t HB_QKV  = HB_H    + (size_t)M_ * D_;
constexpr size_t HB_ATTN = HB_QKV  + (size_t)M_ * 3 * D_;
constexpr size_t HB_H2   = HB_ATTN + (size_t)M_ * D_;
constexpr size_t HB_U1   = HB_H2   + (size_t)M_ * D_;
constexpr size_t HB_U2   = HB_U1   + (size_t)M_ * DFFP2_;
constexpr size_t HB_U    = HB_U2   + (size_t)M_ * DFFP2_;
constexpr size_t HB_W3P  = HB_U    + (size_t)M_ * DFFP2_;
constexpr size_t HB_WQKV = HB_W3P  + (size_t)D_ * DFFP2_;
constexpr size_t HB_WOUT = HB_WQKV + (size_t)3 * D_ * D_;
constexpr size_t HB_W1   = HB_WOUT + (size_t)D_ * D_;
constexpr size_t HB_W2   = HB_W1   + (size_t)DFF_ * D_;
constexpr size_t HB_TOTAL= HB_W2   + (size_t)DFF_ * D_;

__device__ __align__(256) __nv_bfloat16 d_hb[HB_TOTAL];
__device__ int d_idx[M_];
__device__ unsigned long long d_keys[B_ * T_];

// ---------------------------------------------------------------------------
// helpers
// ---------------------------------------------------------------------------
__device__ __forceinline__ void cp_async16(uint32_t dst, const void* src, bool valid) {
    int sz = valid ? 16 : 0;
    asm volatile("cp.async.cg.shared.global [%0], [%1], 16, %2;\n"
                 :: "r"(dst), "l"(src), "r"(sz));
}
__device__ __forceinline__ void ldsm_x4(uint32_t* r, const void* p) {
    uint32_t a = (uint32_t)__cvta_generic_to_shared(p);
    asm volatile("ldmatrix.sync.aligned.m8n8.x4.shared.b16 {%0,%1,%2,%3}, [%4];"
                 : "=r"(r[0]), "=r"(r[1]), "=r"(r[2]), "=r"(r[3]) : "r"(a));
}
__device__ __forceinline__ void ldsm_x2(uint32_t* r, const void* p) {
    uint32_t a = (uint32_t)__cvta_generic_to_shared(p);
    asm volatile("ldmatrix.sync.aligned.m8n8.x2.shared.b16 {%0,%1}, [%2];"
                 : "=r"(r[0]), "=r"(r[1]) : "r"(a));
}
__device__ __forceinline__ void ldsm_x2t(uint32_t* r, const void* p) {
    uint32_t a = (uint32_t)__cvta_generic_to_shared(p);
    asm volatile("ldmatrix.sync.aligned.m8n8.x2.trans.shared.b16 {%0,%1}, [%2];"
                 : "=r"(r[0]), "=r"(r[1]) : "r"(a));
}
__device__ __forceinline__ void mma_bf16(float* c, const uint32_t* a, uint32_t b0, uint32_t b1) {
    asm volatile(
        "mma.sync.aligned.m16n8k16.row.col.f32.bf16.bf16.f32 "
        "{%0,%1,%2,%3}, {%4,%5,%6,%7}, {%8,%9}, {%0,%1,%2,%3};\n"
        : "+f"(c[0]), "+f"(c[1]), "+f"(c[2]), "+f"(c[3])
        : "r"(a[0]), "r"(a[1]), "r"(a[2]), "r"(a[3]), "r"(b0), "r"(b1));
}

// ---------------------------------------------------------------------------
// 1. Router
// ---------------------------------------------------------------------------
__global__ __launch_bounds__(256) void router_kernel(const float* __restrict__ x,
                                                     const float* __restrict__ wr)
{
    int warp = (blockIdx.x * blockDim.x + threadIdx.x) >> 5;
    int lane = threadIdx.x & 31;
    if (warp >= B_ * T_) return;
    const float4* xr  = (const float4*)(x + (size_t)warp * D_);
    const float4* wr4 = (const float4*)wr;
    float acc = 0.f;
    #pragma unroll
    for (int k = lane; k < D_ / 4; k += 32) {
        float4 a = xr[k], w = wr4[k];
        acc += a.x * w.x + a.y * w.y + a.z * w.z + a.w * w.w;
    }
    #pragma unroll
    for (int o = 16; o; o >>= 1) acc += __shfl_xor_sync(0xFFFFFFFFu, acc, o);
    if (lane == 0) d_ws[OFF_SCORES + warp] = acc;
}

// ---------------------------------------------------------------------------
// 2a/2b. Top-k (validated in round 3)
// ---------------------------------------------------------------------------
__global__ __launch_bounds__(256) void topk_sort512_kernel()
{
    __shared__ unsigned long long key[512];
    int chunk = blockIdx.x;
    int b = chunk >> 3;
    int c0 = (chunk & 7) * 512;

    for (int t = threadIdx.x; t < 512; t += 256) {
        int gi = c0 + t;
        float s = d_ws[OFF_SCORES + (size_t)b * T_ + gi];
        unsigned int u = __float_as_uint(s);
        u = (u & 0x80000000u) ? ~u : (u | 0x80000000u);
        key[t] = ((unsigned long long)u << 32) | (unsigned int)(0xFFFFFFFFu - (unsigned)gi);
    }
    __syncthreads();
    for (int k = 2; k <= 512; k <<= 1) {
        for (int j = k >> 1; j > 0; j >>= 1) {
            for (int t = threadIdx.x; t < 512; t += 256) {
                int l = t ^ j;
                if (l > t) {
                    unsigned long long a = key[t], c = key[l];
                    bool desc = ((t & k) == 0);
                    if (desc ? (a < c) : (a > c)) { key[t] = c; key[l] = a; }
                }
            }
            __syncthreads();
        }
    }
    for (int t = threadIdx.x; t < 512; t += 256)
        d_keys[(size_t)b * T_ + c0 + t] = key[t];
}

__global__ __launch_bounds__(512) void topk_merge_kernel()
{
    __shared__ unsigned long long key[T_];
    int b = blockIdx.x;
    for (int t = threadIdx.x; t < T_; t += 512)
        key[t] = d_keys[(size_t)b * T_ + t];
    __syncthreads();

    #pragma unroll
    for (int r = 0; r < 3; r++) {
        int pairs = 4 >> r;
        int stride = 1024 << r;
        int half = 512 << r;
        for (int e = threadIdx.x; e < pairs * 512; e += 512) {
            int p = e >> 9, i = e & 511;
            int base = p * stride;
            unsigned long long a = key[base + i];
            unsigned long long bb = key[base + half + 511 - i];
            if (bb > a) key[base + i] = bb;
        }
        __syncthreads();
        for (int j = 256; j > 0; j >>= 1) {
            for (int e = threadIdx.x; e < pairs * 256; e += 512) {
                int p = e >> 8, q = e & 255;
                int i = ((q & ~(j - 1)) << 1) | (q & (j - 1));
                int base = p * stride;
                unsigned long long a = key[base + i], c = key[base + i + j];
                if (a < c) { key[base + i] = c; key[base + i + j] = a; }
            }
            __syncthreads();
        }
    }
    for (int t = threadIdx.x; t < CAP_; t += 512)
        d_idx[b * CAP_ + t] = (int)(0xFFFFFFFFu - (unsigned int)(key[t] & 0xFFFFFFFFu));
}

// ---------------------------------------------------------------------------
__device__ __forceinline__ float block_reduce_sum_256(float v, float* red)
{
    #pragma unroll
    for (int o = 16; o; o >>= 1) v += __shfl_xor_sync(0xFFFFFFFFu, v, o);
    if ((threadIdx.x & 31) == 0) red[threadIdx.x >> 5] = v;
    __syncthreads();
    float tot = 0.f;
    #pragma unroll
    for (int w = 0; w < 8; w++) tot += red[w];
    return tot;
}

// ---------------------------------------------------------------------------
// 3. Gather + RMSNorm -> XSEL fp32 + Hb bf16
// ---------------------------------------------------------------------------
__global__ __launch_bounds__(256) void gather_rmsnorm_kernel(const float* __restrict__ x,
                                                             const float* __restrict__ g)
{
    __shared__ float red[8];
    int row = blockIdx.x;
    int b = row >> 9;
    int t = d_idx[row];
    int tid = threadIdx.x;
    float4 v = ((const float4*)(x + ((size_t)b * T_ + t) * D_))[tid];
    float ss = v.x*v.x + v.y*v.y + v.z*v.z + v.w*v.w;
    float tot = block_reduce_sum_256(ss, red);
    float rinv = rsqrtf(tot * (1.f / D_) + 1e-6f);
    float4 gv = ((const float4*)g)[tid];
    ((float4*)(d_ws + OFF_XSEL + (size_t)row * D_))[tid] = v;
    __nv_bfloat162* hb = (__nv_bfloat162*)(d_hb + HB_H + (size_t)row * D_);
    hb[tid * 2]     = __floats2bfloat162_rn(v.x * rinv * gv.x, v.y * rinv * gv.y);
    hb[tid * 2 + 1] = __floats2bfloat162_rn(v.z * rinv * gv.z, v.w * rinv * gv.w);
}

// ---------------------------------------------------------------------------
// 4. RMSNorm y1 -> H2b bf16
// ---------------------------------------------------------------------------
__global__ __launch_bounds__(256) void rmsnorm2_kernel(const float* __restrict__ g)
{
    __shared__ float red[8];
    int row = blockIdx.x;
    int tid = threadIdx.x;
    float4 v = ((const float4*)(d_ws + OFF_Y1 + (size_t)row * D_))[tid];
    float ss = v.x*v.x + v.y*v.y + v.z*v.z + v.w*v.w;
    float tot = block_reduce_sum_256(ss, red);
    float rinv = rsqrtf(tot * (1.f / D_) + 1e-6f);
    float4 gv = ((const float4*)g)[tid];
    __nv_bfloat162* hb = (__nv_bfloat162*)(d_hb + HB_H2 + (size_t)row * D_);
    hb[tid * 2]     = __floats2bfloat162_rn(v.x * rinv * gv.x, v.y * rinv * gv.y);
    hb[tid * 2 + 1] = __floats2bfloat162_rn(v.z * rinv * gv.z, v.w * rinv * gv.w);
}

// ---------------------------------------------------------------------------
// 5. BF16 tensor-core GEMM (NT): C = A @ B^T (+ADD). BM=BN=128, BK=32.
//    smem pitch 40 halves (80B): 16B-aligned, conflict-free ldmatrix.
// ---------------------------------------------------------------------------
#define GBM 128
#define GBN 128
#define GBK2 32
#define BPITCH 40

__global__ __launch_bounds__(256) void bf16_gemm_nt(const __nv_bfloat16* __restrict__ A,
                                                    const __nv_bfloat16* __restrict__ Bw,
                                                    void* __restrict__ Cv,
                                                    const float* __restrict__ ADD,
                                                    int M, int N, int K, int ldc,
                                                    int outBf16)
{
    __shared__ __nv_bfloat16 As[2][GBM * BPITCH];
    __shared__ __nv_bfloat16 Bs[2][GBM * BPITCH];

    const int tid  = threadIdx.x;
    const int lane = tid & 31, warp = tid >> 5;
    const int g    = lane >> 2, tg = lane & 3;
    const int wm   = warp >> 2;   // 0..1
    const int wn   = warp & 3;    // 0..3
    const int row0 = blockIdx.y * GBM;
    const int col0 = blockIdx.x * GBN;

    float acc[4][4][4];
    #pragma unroll
    for (int i = 0; i < 4; i++)
        #pragma unroll
        for (int j = 0; j < 4; j++)
            #pragma unroll
            for (int r = 0; r < 4; r++) acc[i][j][r] = 0.f;

    auto issue = [&](int buf, int k0) {
        #pragma unroll
        for (int i = 0; i < 2; i++) {
            int c = tid + 256 * i;
            int r = c >> 2, off = (c & 3) * 8;
            cp_async16((uint32_t)__cvta_generic_to_shared(&As[buf][r * BPITCH + off]),
                       A + (size_t)(row0 + r) * K + k0 + off, true);
            cp_async16((uint32_t)__cvta_generic_to_shared(&Bs[buf][r * BPITCH + off]),
                       Bw + (size_t)(col0 + r) * K + k0 + off, (col0 + r) < N);
        }
        asm volatile("cp.async.commit_group;\n");
    };

    issue(0, 0);
    issue(1, GBK2);

    int buf = 0;
    for (int k0 = 0; k0 < K; k0 += GBK2) {
        if (k0 + GBK2 < K) asm volatile("cp.async.wait_group 1;\n");
        else               asm volatile("cp.async.wait_group 0;\n");
        __syncthreads();

        #pragma unroll
        for (int kk = 0; kk < GBK2; kk += 16) {
            uint32_t af[4][4], bfg[4][2];
            #pragma unroll
            for (int mt = 0; mt < 4; mt++)
                ldsm_x4(af[mt], &As[buf][(wm * 64 + mt * 16 + (lane & 15)) * BPITCH
                                         + kk + ((lane >> 4) << 3)]);
            #pragma unroll
            for (int nt = 0; nt < 4; nt++)
                ldsm_x2(bfg[nt], &Bs[buf][(wn * 32 + nt * 8 + (lane & 7)) * BPITCH
                                          + kk + (((lane >> 3) & 1) << 3)]);
            #pragma unroll
            for (int mt = 0; mt < 4; mt++)
                #pragma unroll
                for (int nt = 0; nt < 4; nt++)
                    mma_bf16(acc[mt][nt], af[mt], bfg[nt][0], bfg[nt][1]);
        }
        __syncthreads();

        if (k0 + 2 * GBK2 < K) issue(buf, k0 + 2 * GBK2);
        buf ^= 1;
    }

    #pragma unroll
    for (int mt = 0; mt < 4; mt++) {
        int r1 = row0 + wm * 64 + mt * 16 + g;
        int r2 = r1 + 8;
        #pragma unroll
        for (int nt = 0; nt < 4; nt++) {
            int c = col0 + wn * 32 + nt * 8 + 2 * tg;
            if (c < N) {
                float2 v0 = make_float2(acc[mt][nt][0], acc[mt][nt][1]);
                float2 v1 = make_float2(acc[mt][nt][2], acc[mt][nt][3]);
                if (ADD) {
                    float2 a0 = *(const float2*)&ADD[(size_t)r1 * ldc + c];
                    float2 a1 = *(const float2*)&ADD[(size_t)r2 * ldc + c];
                    v0.x += a0.x; v0.y += a0.y;
                    v1.x += a1.x; v1.y += a1.y;
                }
                if (outBf16) {
                    __nv_bfloat16* C = (__nv_bfloat16*)Cv;
                    *(__nv_bfloat162*)&C[(size_t)r1 * ldc + c] = __floats2bfloat162_rn(v0.x, v0.y);
                    *(__nv_bfloat162*)&C[(size_t)r2 * ldc + c] = __floats2bfloat162_rn(v1.x, v1.y);
                } else {
                    float* C = (float*)Cv;
                    *(float2*)&C[(size_t)r1 * ldc + c] = v0;
                    *(float2*)&C[(size_t)r2 * ldc + c] = v1;
                }
            }
        }
    }
}

// ---------------------------------------------------------------------------
// 6. Fused flash attention, bf16 mma m16n8k16, online softmax.
//    Block = (bh, q-tile 64). 128 threads / 4 warps, warp owns 16 rows.
// ---------------------------------------------------------------------------
#define AP 72          // bf16 tile pitch (halves): 144B rows, conflict-free
#define SP 68          // fp32 S pitch
constexpr int FA_BF16_HALves = 4 * 64 * AP;             // Q,K,V,P
constexpr int FA_SMEM_BYTES = FA_BF16_HALves * 2 + (64 * SP + 3 * 64) * 4;

__global__ __launch_bounds__(128) void flash_attn_kernel()
{
    extern __shared__ char fsm_raw[];
    __nv_bfloat16* Qs = (__nv_bfloat16*)fsm_raw;
    __nv_bfloat16* Ks = Qs + 64 * AP;
    __nv_bfloat16* Vs = Ks + 64 * AP;
    __nv_bfloat16* Pb = Vs + 64 * AP;
    float* Sf   = (float*)(Pb + 64 * AP);
    float* smM  = Sf + 64 * SP;
    float* smL  = smM + 64;
    float* smSc = smL + 64;

    const int bh = blockIdx.x;
    const int it = 7 - blockIdx.y;
    const int b  = bh >> 4, h = bh & 15;
    const int tid = threadIdx.x;
    const int lane = tid & 31, w = tid >> 5;
    const int g = lane >> 2, tg = lane & 3;
    const int m0 = w * 16;

    const __nv_bfloat16* qkv = d_hb + HB_QKV;
    const int tokQ0 = b * CAP_ + it * 64;

    // load Q tile: 64 rows x 64 halves = 512 x 16B chunks / (8 per row)
    #pragma unroll
    for (int i = 0; i < 4; i++) {
        int c = tid + 128 * i;
        int r = c >> 3, off = (c & 7) * 8;
        cp_async16((uint32_t)__cvta_generic_to_shared(&Qs[r * AP + off]),
                   qkv + (size_t)(tokQ0 + r) * (3 * D_) + h * 64 + off, true);
    }
    asm volatile("cp.async.commit_group;\n");

    if (tid < 64) { smM[tid] = -1e30f; smL[tid] = 0.f; }

    float acc[8][4];
    #pragma unroll
    for (int nt = 0; nt < 8; nt++)
        #pragma unroll
        for (int r = 0; r < 4; r++) acc[nt][r] = 0.f;

    for (int jt = 0; jt <= it; jt++) {
        const int tokK0 = b * CAP_ + jt * 64;
        #pragma unroll
        for (int i = 0; i < 4; i++) {
            int c = tid + 128 * i;
            int r = c >> 3, off = (c & 7) * 8;
            cp_async16((uint32_t)__cvta_generic_to_shared(&Ks[r * AP + off]),
                       qkv + (size_t)(tokK0 + r) * (3 * D_) + D_ + h * 64 + off, true);
            cp_async16((uint32_t)__cvta_generic_to_shared(&Vs[r * AP + off]),
                       qkv + (size_t)(tokK0 + r) * (3 * D_) + 2 * D_ + h * 64 + off, true);
        }
        asm volatile("cp.async.commit_group;\n");
        asm volatile("cp.async.wait_group 0;\n");
        __syncthreads();

        // ---- S = Q K^T ----
        float sacc[8][4];
        #pragma unroll
        for (int nt = 0; nt < 8; nt++)
            #pragma unroll
            for (int r = 0; r < 4; r++) sacc[nt][r] = 0.f;

        #pragma unroll
        for (int kk = 0; kk < 64; kk += 16) {
            uint32_t a[4];
            ldsm_x4(a, &Qs[(m0 + (lane & 15)) * AP + kk + ((lane >> 4) << 3)]);
            #pragma unroll
            for (int nt = 0; nt < 8; nt++) {
                uint32_t bb[2];
                ldsm_x2(bb, &Ks[(nt * 8 + (lane & 7)) * AP + kk + (((lane >> 3) & 1) << 3)]);
                mma_bf16(sacc[nt], a, bb[0], bb[1]);
            }
        }

        // write S (scaled + causal mask on diagonal tile) to fp32 smem
        const bool diag = (jt == it);
        const int r0l = m0 + g, r1l = r0l + 8;
        #pragma unroll
        for (int nt = 0; nt < 8; nt++) {
            int c0 = nt * 8 + 2 * tg, c1 = c0 + 1;
            float s00 = sacc[nt][0] * 0.125f, s01 = sacc[nt][1] * 0.125f;
            float s10 = sacc[nt][2] * 0.125f, s11 = sacc[nt][3] * 0.125f;
            if (diag) {
                if (c0 > r0l) s00 = -1e30f;
                if (c1 > r0l) s01 = -1e30f;
                if (c0 > r1l) s10 = -1e30f;
                if (c1 > r1l) s11 = -1e30f;
            }
            Sf[r0l * SP + c0] = s00; Sf[r0l * SP + c1] = s01;
            Sf[r1l * SP + c0] = s10; Sf[r1l * SP + c1] = s11;
        }
        __syncwarp();

        // ---- online softmax on warp's 16 rows; write P bf16 ----
        {
            int row = m0 + (lane >> 1);
            int cbase = (lane & 1) * 32;
            float* srow = &Sf[row * SP + cbase];
            __nv_bfloat16* prow = &Pb[row * AP + cbase];
            float mloc = -1e30f;
            #pragma unroll
            for (int c = 0; c < 32; c++) mloc = fmaxf(mloc, srow[c]);
            mloc = fmaxf(mloc, __shfl_xor_sync(0xFFFFFFFFu, mloc, 1));
            float mOld = smM[row];
            float mNew = fmaxf(mOld, mloc);
            float sc = __expf(mOld - mNew);
            float s = 0.f;
            #pragma unroll
            for (int c = 0; c < 32; c++) {
                float e = __expf(srow[c] - mNew);
                prow[c] = __float2bfloat16(e);
                s += e;
            }
            s += __shfl_xor_sync(0xFFFFFFFFu, s, 1);
            if ((lane & 1) == 0) {
                smM[row]  = mNew;
                smL[row]  = smL[row] * sc + s;
                smSc[row] = sc;
            }
        }
        __syncwarp();

        // ---- rescale, then O += P V ----
        {
            float sc0 = smSc[m0 + g], sc1 = smSc[m0 + g + 8];
            #pragma unroll
            for (int nt = 0; nt < 8; nt++) {
                acc[nt][0] *= sc0; acc[nt][1] *= sc0;
                acc[nt][2] *= sc1; acc[nt][3] *= sc1;
            }
        }
        #pragma unroll
        for (int kk = 0; kk < 64; kk += 16) {
            uint32_t a[4];
            ldsm_x4(a, &Pb[(m0 + (lane & 15)) * AP + kk + ((lane >> 4) << 3)]);
            #pragma unroll
            for (int nt = 0; nt < 8; nt++) {
                uint32_t bb[2];
                ldsm_x2t(bb, &Vs[(kk + (lane & 15)) * AP + nt * 8]);
                mma_bf16(acc[nt], a, bb[0], bb[1]);
            }
        }
        __syncthreads();   // protect Ks/Vs for next jt
    }

    // ---- finalize ----
    float inv0 = 1.f / smL[m0 + g];
    float inv1 = 1.f / smL[m0 + g + 8];
    __nv_bfloat16* O = d_hb + HB_ATTN;
    int tok0 = tokQ0 + m0 + g;
    #pragma unroll
    for (int nt = 0; nt < 8; nt++) {
        int c = h * 64 + nt * 8 + 2 * tg;
        *(__nv_bfloat162*)&O[(size_t)tok0 * D_ + c] =
            __floats2bfloat162_rn(acc[nt][0] * inv0, acc[nt][1] * inv0);
        *(__nv_bfloat162*)&O[(size_t)(tok0 + 8) * D_ + c] =
            __floats2bfloat162_rn(acc[nt][2] * inv1, acc[nt][3] * inv1);
    }
}

// ---------------------------------------------------------------------------
// 7. SwiGLU: Ub = silu(U1b) * U2b (bf16 in/out, zero pad)
// ---------------------------------------------------------------------------
__global__ __launch_bounds__(256) void swiglu_kernel()
{
    size_t e = (size_t)blockIdx.x * blockDim.x + threadIdx.x;
    if (e >= (size_t)M_ * DFFP2_) return;
    int n = (int)(e % DFFP2_);
    float val = 0.f;
    if (n < DFF_) {
        float a = __bfloat162float(d_hb[HB_U1 + e]);
        float c = __bfloat162float(d_hb[HB_U2 + e]);
        val = a / (1.f + __expf(-a)) * c;
    }
    d_hb[HB_U + e] = __float2bfloat16(val);
}

// ---------------------------------------------------------------------------
// 8. Weight prep
// ---------------------------------------------------------------------------
__global__ __launch_bounds__(256) void conv_bf16_kernel(__nv_bfloat16* __restrict__ dst,
                                                        const float* __restrict__ src,
                                                        size_t n4)
{
    size_t i = (size_t)blockIdx.x * blockDim.x + threadIdx.x;
    if (i >= n4) return;
    float4 v = ((const float4*)src)[i];
    ((__nv_bfloat162*)dst)[i * 2]     = __floats2bfloat162_rn(v.x, v.y);
    ((__nv_bfloat162*)dst)[i * 2 + 1] = __floats2bfloat162_rn(v.z, v.w);
}

__global__ __launch_bounds__(256) void repack_w3_kernel(const float* __restrict__ W3)
{
    size_t e = (size_t)blockIdx.x * blockDim.x + threadIdx.x;
    if (e >= (size_t)D_ * DFFP2_) return;
    int n = (int)(e / DFFP2_);
    int k = (int)(e - (size_t)n * DFFP2_);
    d_hb[HB_W3P + e] = __float2bfloat16((k < DFF_) ? W3[(size_t)n * DFF_ + k] : 0.f);
}

// ---------------------------------------------------------------------------
// 9. copy + scatter
// ---------------------------------------------------------------------------
__global__ __launch_bounds__(256) void copy_kernel(float* __restrict__ out,
                                                   const float* __restrict__ x)
{
    size_t i = (size_t)blockIdx.x * blockDim.x + threadIdx.x;
    if (i < (size_t)B_ * T_ * D_ / 4)
        ((float4*)out)[i] = ((const float4*)x)[i];
}

__global__ __launch_bounds__(256) void scatter_kernel(float* __restrict__ out)
{
    int row = blockIdx.x;
    int tid = threadIdx.x;
    int b = row >> 9;
    int t = d_idx[row];
    float4 v = ((const float4*)(d_ws + OFF_XPROC + (size_t)row * D_))[tid];
    ((float4*)(out + ((size_t)b * T_ + t) * D_))[tid] = v;
}

// ---------------------------------------------------------------------------
// Launcher
// ---------------------------------------------------------------------------
extern "C" void kernel_launch(void* const* d_in, const int* in_sizes, int n_in,
                              void* d_out, int out_size)
{
    const float* x    = (const float*)d_in[0];
    const float* wr   = (const float*)d_in[1];
    const float* Wqkv = (const float*)d_in[2];
    const float* Wout = (const float*)d_in[3];
    const float* g1   = (const float*)d_in[4];
    const float* g2   = (const float*)d_in[5];
    const float* W1   = (const float*)d_in[6];
    const float* W2   = (const float*)d_in[7];
    const float* W3   = (const float*)d_in[8];
    float* out = (float*)d_out;

    float* ws = nullptr;
    __nv_bfloat16* hb = nullptr;
    cudaGetSymbolAddress((void**)&ws, d_ws);
    cudaGetSymbolAddress((void**)&hb, d_hb);
    cudaFuncSetAttribute(flash_attn_kernel,
                         cudaFuncAttributeMaxDynamicSharedMemorySize, FA_SMEM_BYTES);

    auto cv = [&](size_t off, const float* src, size_t n) {
        conv_bf16_kernel<<<(int)((n / 4 + 255) / 256), 256>>>(hb + off, src, n / 4);
    };

    // independent prep
    copy_kernel<<<(B_ * T_ * D_ / 4 + 255) / 256, 256>>>(out, x);
    repack_w3_kernel<<<(int)(((size_t)D_ * DFFP2_ + 255) / 256), 256>>>(W3);
    cv(HB_WQKV, Wqkv, (size_t)3 * D_ * D_);
    cv(HB_WOUT, Wout, (size_t)D_ * D_);
    cv(HB_W1,   W1,   (size_t)DFF_ * D_);
    cv(HB_W2,   W2,   (size_t)DFF_ * D_);

    // routing
    router_kernel<<<(B_ * T_ * 32 + 255) / 256, 256>>>(x, wr);
    topk_sort512_kernel<<<32, 256>>>();
    topk_merge_kernel<<<B_, 512>>>();

    gather_rmsnorm_kernel<<<M_, 256>>>(x, g1);

    // QKV projection -> bf16
    bf16_gemm_nt<<<dim3(3 * D_ / GBN, M_ / GBM), 256>>>(hb + HB_H, hb + HB_WQKV,
                                                        hb + HB_QKV, nullptr,
                                                        M_, 3 * D_, D_, 3 * D_, 1);

    flash_attn_kernel<<<dim3(B_ * H_, 8), 128, FA_SMEM_BYTES>>>();

    // out projection + residual -> fp32 Y1
    bf16_gemm_nt<<<dim3(D_ / GBN, M_ / GBM), 256>>>(hb + HB_ATTN, hb + HB_WOUT,
                                                    ws + OFF_Y1, ws + OFF_XSEL,
                                                    M_, D_, D_, D_, 0);

    rmsnorm2_kernel<<<M_, 256>>>(g2);

    // FFN up projections -> bf16
    bf16_gemm_nt<<<dim3((DFF_ + GBN - 1) / GBN, M_ / GBM), 256>>>(hb + HB_H2, hb + HB_W1,
                                                                  hb + HB_U1, nullptr,
                                                                  M_, DFF_, D_, DFFP2_, 1);
    bf16_gemm_nt<<<dim3((DFF_ + GBN - 1) / GBN, M_ / GBM), 256>>>(hb + HB_H2, hb + HB_W2,
                                                                  hb + HB_U2, nullptr,
                                                                  M_, DFF_, D_, DFFP2_, 1);
    swiglu_kernel<<<(int)(((size_t)M_ * DFFP2_ + 255) / 256), 256>>>();

    // down projection + residual -> fp32 XPROC
    bf16_gemm_nt<<<dim3(D_ / GBN, M_ / GBM), 256>>>(hb + HB_U, hb + HB_W3P,
                                                    ws + OFF_XPROC, ws + OFF_Y1,
                                                    M_, D_, DFFP2_, D_, 0);

    scatter_kernel<<<M_, 256>>>(out);
}

// round 6
// speedup vs baseline: 5.2529x; 1.0950x over previous
#include <cuda_runtime.h>
#include <cuda_bf16.h>
#include <cstdint>
#include <cmath>

#define B_ 4
#define T_ 4096
#define D_ 1024
#define H_ 16
#define HD_ 64
#define CAP_ 512
#define M_ 2048
#define DFF_ 2730
#define DFF2_ 5460          // 2*DFF (fused W1|W2 GEMM N)
#define LD12_ 5472          // row pitch of fused U12 output (mult of 32)
#define DFFP2_ 2752         // padded K for W3 GEMM (mult of 32)

// ---------------------------------------------------------------------------
// fp32 workspace
// ---------------------------------------------------------------------------
constexpr size_t OFF_SCORES = 0;
constexpr size_t OFF_XSEL   = OFF_SCORES + (size_t)B_ * T_;
constexpr size_t OFF_Y1     = OFF_XSEL   + (size_t)M_ * D_;
constexpr size_t OFF_XPROC  = OFF_Y1     + (size_t)M_ * D_;
constexpr size_t WS_TOTAL   = OFF_XPROC  + (size_t)M_ * D_;

__device__ __align__(256) float d_ws[WS_TOTAL];

// bf16 workspace
constexpr size_t HB_H    = 0;
constexpr size_t HB_QKV  = HB_H    + (size_t)M_ * D_;
constexpr size_t HB_ATTN = HB_QKV  + (size_t)M_ * 3 * D_;
constexpr size_t HB_H2   = HB_ATTN + (size_t)M_ * D_;
constexpr size_t HB_U12  = HB_H2   + (size_t)M_ * D_;
constexpr size_t HB_U    = HB_U12  + (size_t)M_ * LD12_;
constexpr size_t HB_W3P  = HB_U    + (size_t)M_ * DFFP2_;
constexpr size_t HB_WQKV = HB_W3P  + (size_t)D_ * DFFP2_;
constexpr size_t HB_WOUT = HB_WQKV + (size_t)3 * D_ * D_;
constexpr size_t HB_W12  = HB_WOUT + (size_t)D_ * D_;
constexpr size_t HB_TOTAL= HB_W12  + (size_t)DFF2_ * D_;

__device__ __align__(256) __nv_bfloat16 d_hb[HB_TOTAL];
__device__ int d_idx[M_];
__device__ unsigned long long d_keys[B_ * T_];

// ---------------------------------------------------------------------------
// helpers
// ---------------------------------------------------------------------------
__device__ __forceinline__ void cp_async16(uint32_t dst, const void* src, bool valid) {
    int sz = valid ? 16 : 0;
    asm volatile("cp.async.cg.shared.global [%0], [%1], 16, %2;\n"
                 :: "r"(dst), "l"(src), "r"(sz));
}
__device__ __forceinline__ void ldsm_x4(uint32_t* r, const void* p) {
    uint32_t a = (uint32_t)__cvta_generic_to_shared(p);
    asm volatile("ldmatrix.sync.aligned.m8n8.x4.shared.b16 {%0,%1,%2,%3}, [%4];"
                 : "=r"(r[0]), "=r"(r[1]), "=r"(r[2]), "=r"(r[3]) : "r"(a));
}
__device__ __forceinline__ void ldsm_x2(uint32_t* r, const void* p) {
    uint32_t a = (uint32_t)__cvta_generic_to_shared(p);
    asm volatile("ldmatrix.sync.aligned.m8n8.x2.shared.b16 {%0,%1}, [%2];"
                 : "=r"(r[0]), "=r"(r[1]) : "r"(a));
}
__device__ __forceinline__ void ldsm_x2t(uint32_t* r, const void* p) {
    uint32_t a = (uint32_t)__cvta_generic_to_shared(p);
    asm volatile("ldmatrix.sync.aligned.m8n8.x2.trans.shared.b16 {%0,%1}, [%2];"
                 : "=r"(r[0]), "=r"(r[1]) : "r"(a));
}
__device__ __forceinline__ void mma_bf16(float* c, const uint32_t* a, uint32_t b0, uint32_t b1) {
    asm volatile(
        "mma.sync.aligned.m16n8k16.row.col.f32.bf16.bf16.f32 "
        "{%0,%1,%2,%3}, {%4,%5,%6,%7}, {%8,%9}, {%0,%1,%2,%3};\n"
        : "+f"(c[0]), "+f"(c[1]), "+f"(c[2]), "+f"(c[3])
        : "r"(a[0]), "r"(a[1]), "r"(a[2]), "r"(a[3]), "r"(b0), "r"(b1));
}

// ---------------------------------------------------------------------------
// block reduce (256 threads)
// ---------------------------------------------------------------------------
__device__ __forceinline__ float block_reduce_sum_256(float v, float* red)
{
    #pragma unroll
    for (int o = 16; o; o >>= 1) v += __shfl_xor_sync(0xFFFFFFFFu, v, o);
    if ((threadIdx.x & 31) == 0) red[threadIdx.x >> 5] = v;
    __syncthreads();
    float tot = 0.f;
    #pragma unroll
    for (int w = 0; w < 8; w++) tot += red[w];
    return tot;
}

// ---------------------------------------------------------------------------
// 1. Fused copy (out = x) + router scores. One block per token, x read once.
// ---------------------------------------------------------------------------
__global__ __launch_bounds__(256) void copy_router_kernel(float* __restrict__ out,
                                                          const float* __restrict__ x,
                                                          const float* __restrict__ wr)
{
    __shared__ float red[8];
    int tok = blockIdx.x;                     // 0..B_*T_-1
    int tid = threadIdx.x;
    float4 v = ((const float4*)(x + (size_t)tok * D_))[tid];
    ((float4*)(out + (size_t)tok * D_))[tid] = v;
    float4 w = ((const float4*)wr)[tid];
    float dot = v.x * w.x + v.y * w.y + v.z * w.z + v.w * w.w;
    float tot = block_reduce_sum_256(dot, red);
    if (tid == 0) d_ws[OFF_SCORES + tok] = tot;
}

// ---------------------------------------------------------------------------
// 2. Top-k (validated)
// ---------------------------------------------------------------------------
__global__ __launch_bounds__(256) void topk_sort512_kernel()
{
    __shared__ unsigned long long key[512];
    int chunk = blockIdx.x;
    int b = chunk >> 3;
    int c0 = (chunk & 7) * 512;

    for (int t = threadIdx.x; t < 512; t += 256) {
        int gi = c0 + t;
        float s = d_ws[OFF_SCORES + (size_t)b * T_ + gi];
        unsigned int u = __float_as_uint(s);
        u = (u & 0x80000000u) ? ~u : (u | 0x80000000u);
        key[t] = ((unsigned long long)u << 32) | (unsigned int)(0xFFFFFFFFu - (unsigned)gi);
    }
    __syncthreads();
    for (int k = 2; k <= 512; k <<= 1) {
        for (int j = k >> 1; j > 0; j >>= 1) {
            for (int t = threadIdx.x; t < 512; t += 256) {
                int l = t ^ j;
                if (l > t) {
                    unsigned long long a = key[t], c = key[l];
                    bool desc = ((t & k) == 0);
                    if (desc ? (a < c) : (a > c)) { key[t] = c; key[l] = a; }
                }
            }
            __syncthreads();
        }
    }
    for (int t = threadIdx.x; t < 512; t += 256)
        d_keys[(size_t)b * T_ + c0 + t] = key[t];
}

__global__ __launch_bounds__(512) void topk_merge_kernel()
{
    __shared__ unsigned long long key[T_];
    int b = blockIdx.x;
    for (int t = threadIdx.x; t < T_; t += 512)
        key[t] = d_keys[(size_t)b * T_ + t];
    __syncthreads();

    #pragma unroll
    for (int r = 0; r < 3; r++) {
        int pairs = 4 >> r;
        int stride = 1024 << r;
        int half = 512 << r;
        for (int e = threadIdx.x; e < pairs * 512; e += 512) {
            int p = e >> 9, i = e & 511;
            int base = p * stride;
            unsigned long long a = key[base + i];
            unsigned long long bb = key[base + half + 511 - i];
            if (bb > a) key[base + i] = bb;
        }
        __syncthreads();
        for (int j = 256; j > 0; j >>= 1) {
            for (int e = threadIdx.x; e < pairs * 256; e += 512) {
                int p = e >> 8, q = e & 255;
                int i = ((q & ~(j - 1)) << 1) | (q & (j - 1));
                int base = p * stride;
                unsigned long long a = key[base + i], c = key[base + i + j];
                if (a < c) { key[base + i] = c; key[base + i + j] = a; }
            }
            __syncthreads();
        }
    }
    for (int t = threadIdx.x; t < CAP_; t += 512)
        d_idx[b * CAP_ + t] = (int)(0xFFFFFFFFu - (unsigned int)(key[t] & 0xFFFFFFFFu));
}

// ---------------------------------------------------------------------------
// 3. Gather + RMSNorm
// ---------------------------------------------------------------------------
__global__ __launch_bounds__(256) void gather_rmsnorm_kernel(const float* __restrict__ x,
                                                             const float* __restrict__ g)
{
    __shared__ float red[8];
    int row = blockIdx.x;
    int b = row >> 9;
    int t = d_idx[row];
    int tid = threadIdx.x;
    float4 v = ((const float4*)(x + ((size_t)b * T_ + t) * D_))[tid];
    float ss = v.x*v.x + v.y*v.y + v.z*v.z + v.w*v.w;
    float tot = block_reduce_sum_256(ss, red);
    float rinv = rsqrtf(tot * (1.f / D_) + 1e-6f);
    float4 gv = ((const float4*)g)[tid];
    ((float4*)(d_ws + OFF_XSEL + (size_t)row * D_))[tid] = v;
    __nv_bfloat162* hb = (__nv_bfloat162*)(d_hb + HB_H + (size_t)row * D_);
    hb[tid * 2]     = __floats2bfloat162_rn(v.x * rinv * gv.x, v.y * rinv * gv.y);
    hb[tid * 2 + 1] = __floats2bfloat162_rn(v.z * rinv * gv.z, v.w * rinv * gv.w);
}

// ---------------------------------------------------------------------------
// 4. RMSNorm y1 -> H2b
// ---------------------------------------------------------------------------
__global__ __launch_bounds__(256) void rmsnorm2_kernel(const float* __restrict__ g)
{
    __shared__ float red[8];
    int row = blockIdx.x;
    int tid = threadIdx.x;
    float4 v = ((const float4*)(d_ws + OFF_Y1 + (size_t)row * D_))[tid];
    float ss = v.x*v.x + v.y*v.y + v.z*v.z + v.w*v.w;
    float tot = block_reduce_sum_256(ss, red);
    float rinv = rsqrtf(tot * (1.f / D_) + 1e-6f);
    float4 gv = ((const float4*)g)[tid];
    __nv_bfloat162* hb = (__nv_bfloat162*)(d_hb + HB_H2 + (size_t)row * D_);
    hb[tid * 2]     = __floats2bfloat162_rn(v.x * rinv * gv.x, v.y * rinv * gv.y);
    hb[tid * 2 + 1] = __floats2bfloat162_rn(v.z * rinv * gv.z, v.w * rinv * gv.w);
}

// ---------------------------------------------------------------------------
// 5. BF16 mma.sync GEMM (NT): C = A @ B^T (+ADD).
//    BM=BN=128, BK=32, 256 threads (8 warps 2x4; warp tile 64x32).
//    3-stage cp.async ring; B fragments via ldmatrix.x4 pairs.
// ---------------------------------------------------------------------------
#define GBK2 32
#define BPITCH 40
#define G_NST 3
constexpr int G_STAGE_HALVES = 2 * 128 * BPITCH;        // A + B, one stage
constexpr int G_SMEM_BYTES   = G_NST * G_STAGE_HALVES * 2;   // 61440

__global__ __launch_bounds__(256) void bf16_gemm_nt(const __nv_bfloat16* __restrict__ A,
                                                    const __nv_bfloat16* __restrict__ Bw,
                                                    void* __restrict__ Cv,
                                                    const float* __restrict__ ADD,
                                                    int M, int N, int K, int ldc,
                                                    int outBf16)
{
    extern __shared__ __nv_bfloat16 gs[];

    const int tid  = threadIdx.x;
    const int lane = tid & 31, warp = tid >> 5;
    const int g    = lane >> 2, tg = lane & 3;
    const int wm   = warp >> 2;   // 0..1
    const int wn   = warp & 3;    // 0..3
    const int row0 = blockIdx.y * 128;
    const int col0 = blockIdx.x * 128;
    const int nk   = K / GBK2;

    float acc[4][4][4];
    #pragma unroll
    for (int i = 0; i < 4; i++)
        #pragma unroll
        for (int j = 0; j < 4; j++)
            #pragma unroll
            for (int r = 0; r < 4; r++) acc[i][j][r] = 0.f;

    auto issue = [&](int s, int ki) {
        __nv_bfloat16* As = gs + s * G_STAGE_HALVES;
        __nv_bfloat16* Bs = As + 128 * BPITCH;
        int k0 = ki * GBK2;
        #pragma unroll
        for (int i = 0; i < 2; i++) {
            int c = tid + 256 * i;
            int r = c >> 2, off = (c & 3) * 8;
            cp_async16((uint32_t)__cvta_generic_to_shared(&As[r * BPITCH + off]),
                       A + (size_t)(row0 + r) * K + k0 + off, true);
            cp_async16((uint32_t)__cvta_generic_to_shared(&Bs[r * BPITCH + off]),
                       Bw + (size_t)(col0 + r) * K + k0 + off, (col0 + r) < N);
        }
        asm volatile("cp.async.commit_group;\n");
    };

    issue(0, 0);
    issue(1, 1);
    issue(2, 2);

    for (int i = 0; i < nk; i++) {
        int s = i - (i / G_NST) * G_NST;
        int issued = (i + G_NST < nk) ? (i + G_NST) : nk;
        int pend = issued - i - 1;
        if (pend >= 2)      asm volatile("cp.async.wait_group 2;\n");
        else if (pend == 1) asm volatile("cp.async.wait_group 1;\n");
        else                asm volatile("cp.async.wait_group 0;\n");
        __syncthreads();

        const __nv_bfloat16* As = gs + s * G_STAGE_HALVES;
        const __nv_bfloat16* Bs = As + 128 * BPITCH;

        #pragma unroll
        for (int kk = 0; kk < GBK2; kk += 16) {
            uint32_t af[4][4];
            #pragma unroll
            for (int mt = 0; mt < 4; mt++)
                ldsm_x4(af[mt], &As[(wm * 64 + mt * 16 + (lane & 15)) * BPITCH
                                    + kk + ((lane >> 4) << 3)]);
            #pragma unroll
            for (int pb = 0; pb < 2; pb++) {
                // x4 over 16 B-rows: m0=n(0-7)k(0-7) m1=n(8-15)k(0-7)
                //                    m2=n(0-7)k(8-15) m3=n(8-15)k(8-15)
                uint32_t bq[4];
                ldsm_x4(bq, &Bs[(wn * 32 + pb * 16 + (lane & 7) + ((lane >> 3) & 1) * 8) * BPITCH
                                + kk + ((lane >> 4) << 3)]);
                #pragma unroll
                for (int mt = 0; mt < 4; mt++) {
                    mma_bf16(acc[mt][pb * 2],     af[mt], bq[0], bq[2]);
                    mma_bf16(acc[mt][pb * 2 + 1], af[mt], bq[1], bq[3]);
                }
            }
        }
        __syncthreads();

        if (i + G_NST < nk) issue(s, i + G_NST);
    }

    #pragma unroll
    for (int mt = 0; mt < 4; mt++) {
        int r1 = row0 + wm * 64 + mt * 16 + g;
        int r2 = r1 + 8;
        #pragma unroll
        for (int nt = 0; nt < 4; nt++) {
            int c = col0 + wn * 32 + nt * 8 + 2 * tg;
            if (c < N) {
                float2 v0 = make_float2(acc[mt][nt][0], acc[mt][nt][1]);
                float2 v1 = make_float2(acc[mt][nt][2], acc[mt][nt][3]);
                if (ADD) {
                    float2 a0 = *(const float2*)&ADD[(size_t)r1 * ldc + c];
                    float2 a1 = *(const float2*)&ADD[(size_t)r2 * ldc + c];
                    v0.x += a0.x; v0.y += a0.y;
                    v1.x += a1.x; v1.y += a1.y;
                }
                if (outBf16) {
                    __nv_bfloat16* C = (__nv_bfloat16*)Cv;
                    *(__nv_bfloat162*)&C[(size_t)r1 * ldc + c] = __floats2bfloat162_rn(v0.x, v0.y);
                    *(__nv_bfloat162*)&C[(size_t)r2 * ldc + c] = __floats2bfloat162_rn(v1.x, v1.y);
                } else {
                    float* C = (float*)Cv;
                    *(float2*)&C[(size_t)r1 * ldc + c] = v0;
                    *(float2*)&C[(size_t)r2 * ldc + c] = v1;
                }
            }
        }
    }
}

// ---------------------------------------------------------------------------
// 6. Fused flash attention (bf16 mma.sync, validated round 4)
// ---------------------------------------------------------------------------
#define AP 72
#define SP 68
constexpr int FA_SMEM_BYTES = (4 * 64 * AP) * 2 + (64 * SP + 3 * 64) * 4;

__global__ __launch_bounds__(128) void flash_attn_kernel()
{
    extern __shared__ char fsm_raw[];
    __nv_bfloat16* Qs = (__nv_bfloat16*)fsm_raw;
    __nv_bfloat16* Ks = Qs + 64 * AP;
    __nv_bfloat16* Vs = Ks + 64 * AP;
    __nv_bfloat16* Pb = Vs + 64 * AP;
    float* Sf   = (float*)(Pb + 64 * AP);
    float* smM  = Sf + 64 * SP;
    float* smL  = smM + 64;
    float* smSc = smL + 64;

    const int bh = blockIdx.x;
    const int it = 7 - blockIdx.y;
    const int b  = bh >> 4, h = bh & 15;
    const int tid = threadIdx.x;
    const int lane = tid & 31, w = tid >> 5;
    const int g = lane >> 2, tg = lane & 3;
    const int m0 = w * 16;

    const __nv_bfloat16* qkv = d_hb + HB_QKV;
    const int tokQ0 = b * CAP_ + it * 64;

    #pragma unroll
    for (int i = 0; i < 4; i++) {
        int c = tid + 128 * i;
        int r = c >> 3, off = (c & 7) * 8;
        cp_async16((uint32_t)__cvta_generic_to_shared(&Qs[r * AP + off]),
                   qkv + (size_t)(tokQ0 + r) * (3 * D_) + h * 64 + off, true);
    }
    asm volatile("cp.async.commit_group;\n");

    if (tid < 64) { smM[tid] = -1e30f; smL[tid] = 0.f; }

    float acc[8][4];
    #pragma unroll
    for (int nt = 0; nt < 8; nt++)
        #pragma unroll
        for (int r = 0; r < 4; r++) acc[nt][r] = 0.f;

    for (int jt = 0; jt <= it; jt++) {
        const int tokK0 = b * CAP_ + jt * 64;
        #pragma unroll
        for (int i = 0; i < 4; i++) {
            int c = tid + 128 * i;
            int r = c >> 3, off = (c & 7) * 8;
            cp_async16((uint32_t)__cvta_generic_to_shared(&Ks[r * AP + off]),
                       qkv + (size_t)(tokK0 + r) * (3 * D_) + D_ + h * 64 + off, true);
            cp_async16((uint32_t)__cvta_generic_to_shared(&Vs[r * AP + off]),
                       qkv + (size_t)(tokK0 + r) * (3 * D_) + 2 * D_ + h * 64 + off, true);
        }
        asm volatile("cp.async.commit_group;\n");
        asm volatile("cp.async.wait_group 0;\n");
        __syncthreads();

        float sacc[8][4];
        #pragma unroll
        for (int nt = 0; nt < 8; nt++)
            #pragma unroll
            for (int r = 0; r < 4; r++) sacc[nt][r] = 0.f;

        #pragma unroll
        for (int kk = 0; kk < 64; kk += 16) {
            uint32_t a[4];
            ldsm_x4(a, &Qs[(m0 + (lane & 15)) * AP + kk + ((lane >> 4) << 3)]);
            #pragma unroll
            for (int nt = 0; nt < 8; nt++) {
                uint32_t bb[2];
                ldsm_x2(bb, &Ks[(nt * 8 + (lane & 7)) * AP + kk + (((lane >> 3) & 1) << 3)]);
                mma_bf16(sacc[nt], a, bb[0], bb[1]);
            }
        }

        const bool diag = (jt == it);
        const int r0l = m0 + g, r1l = r0l + 8;
        #pragma unroll
        for (int nt = 0; nt < 8; nt++) {
            int c0 = nt * 8 + 2 * tg, c1 = c0 + 1;
            float s00 = sacc[nt][0] * 0.125f, s01 = sacc[nt][1] * 0.125f;
            float s10 = sacc[nt][2] * 0.125f, s11 = sacc[nt][3] * 0.125f;
            if (diag) {
                if (c0 > r0l) s00 = -1e30f;
                if (c1 > r0l) s01 = -1e30f;
                if (c0 > r1l) s10 = -1e30f;
                if (c1 > r1l) s11 = -1e30f;
            }
            Sf[r0l * SP + c0] = s00; Sf[r0l * SP + c1] = s01;
            Sf[r1l * SP + c0] = s10; Sf[r1l * SP + c1] = s11;
        }
        __syncwarp();

        {
            int row = m0 + (lane >> 1);
            int cbase = (lane & 1) * 32;
            float* srow = &Sf[row * SP + cbase];
            __nv_bfloat16* prow = &Pb[row * AP + cbase];
            float mloc = -1e30f;
            #pragma unroll
            for (int c = 0; c < 32; c++) mloc = fmaxf(mloc, srow[c]);
            mloc = fmaxf(mloc, __shfl_xor_sync(0xFFFFFFFFu, mloc, 1));
            float mOld = smM[row];
            float mNew = fmaxf(mOld, mloc);
            float sc = __expf(mOld - mNew);
            float s = 0.f;
            #pragma unroll
            for (int c = 0; c < 32; c++) {
                float e = __expf(srow[c] - mNew);
                prow[c] = __float2bfloat16(e);
                s += e;
            }
            s += __shfl_xor_sync(0xFFFFFFFFu, s, 1);
            if ((lane & 1) == 0) {
                smM[row]  = mNew;
                smL[row]  = smL[row] * sc + s;
                smSc[row] = sc;
            }
        }
        __syncwarp();

        {
            float sc0 = smSc[m0 + g], sc1 = smSc[m0 + g + 8];
            #pragma unroll
            for (int nt = 0; nt < 8; nt++) {
                acc[nt][0] *= sc0; acc[nt][1] *= sc0;
                acc[nt][2] *= sc1; acc[nt][3] *= sc1;
            }
        }
        #pragma unroll
        for (int kk = 0; kk < 64; kk += 16) {
            uint32_t a[4];
            ldsm_x4(a, &Pb[(m0 + (lane & 15)) * AP + kk + ((lane >> 4) << 3)]);
            #pragma unroll
            for (int nt = 0; nt < 8; nt++) {
                uint32_t bb[2];
                ldsm_x2t(bb, &Vs[(kk + (lane & 15)) * AP + nt * 8]);
                mma_bf16(acc[nt], a, bb[0], bb[1]);
            }
        }
        __syncthreads();
    }

    float inv0 = 1.f / smL[m0 + g];
    float inv1 = 1.f / smL[m0 + g + 8];
    __nv_bfloat16* O = d_hb + HB_ATTN;
    int tok0 = tokQ0 + m0 + g;
    #pragma unroll
    for (int nt = 0; nt < 8; nt++) {
        int c = h * 64 + nt * 8 + 2 * tg;
        *(__nv_bfloat162*)&O[(size_t)tok0 * D_ + c] =
            __floats2bfloat162_rn(acc[nt][0] * inv0, acc[nt][1] * inv0);
        *(__nv_bfloat162*)&O[(size_t)(tok0 + 8) * D_ + c] =
            __floats2bfloat162_rn(acc[nt][2] * inv1, acc[nt][3] * inv1);
    }
}

// ---------------------------------------------------------------------------
// 7. SwiGLU from fused U12 (vectorized bf16x2): U = silu(U12[:,0:DFF]) * U12[:,DFF:2DFF]
// ---------------------------------------------------------------------------
#define NPAIR (DFFP2_ / 2)          // 1376 output pairs per row

__global__ __launch_bounds__(256) void swiglu2_kernel()
{
    int i = blockIdx.x * 256 + threadIdx.x;
    if (i >= M_ * NPAIR) return;
    int m = i / NPAIR, p = i - m * NPAIR;
    __nv_bfloat162 r = __floats2bfloat162_rn(0.f, 0.f);
    if (p < DFF_ / 2) {
        const __nv_bfloat16* base = d_hb + HB_U12 + (size_t)m * LD12_;
        __nv_bfloat162 a2 = *(const __nv_bfloat162*)(base + 2 * p);
        __nv_bfloat162 c2 = *(const __nv_bfloat162*)(base + DFF_ + 2 * p);
        float a0 = __bfloat162float(a2.x), a1 = __bfloat162float(a2.y);
        float c0 = __bfloat162float(c2.x), c1 = __bfloat162float(c2.y);
        float v0 = a0 / (1.f + __expf(-a0)) * c0;
        float v1 = a1 / (1.f + __expf(-a1)) * c1;
        r = __floats2bfloat162_rn(v0, v1);
    }
    *(__nv_bfloat162*)(d_hb + HB_U + (size_t)m * DFFP2_ + 2 * p) = r;
}

// ---------------------------------------------------------------------------
// 8. Weight prep
// ---------------------------------------------------------------------------
__global__ __launch_bounds__(256) void conv_bf16_kernel(__nv_bfloat16* __restrict__ dst,
                                                        const float* __restrict__ src,
                                                        size_t n4)
{
    size_t i = (size_t)blockIdx.x * blockDim.x + threadIdx.x;
    if (i >= n4) return;
    float4 v = ((const float4*)src)[i];
    ((__nv_bfloat162*)dst)[i * 2]     = __floats2bfloat162_rn(v.x, v.y);
    ((__nv_bfloat162*)dst)[i * 2 + 1] = __floats2bfloat162_rn(v.z, v.w);
}

// W12 = [W1; W2] -> bf16 [DFF2_, D_]
__global__ __launch_bounds__(256) void conv_w12_kernel(const float* __restrict__ W1,
                                                       const float* __restrict__ W2)
{
    size_t i = (size_t)blockIdx.x * blockDim.x + threadIdx.x;   // float4 index
    if (i >= (size_t)DFF2_ * D_ / 4) return;
    int row = (int)(i >> 8);             // D_/4 = 256
    int c4  = (int)(i & 255);
    const float* src = (row < DFF_) ? (W1 + (size_t)row * D_)
                                    : (W2 + (size_t)(row - DFF_) * D_);
    float4 v = ((const float4*)src)[c4];
    __nv_bfloat162* d = (__nv_bfloat162*)(d_hb + HB_W12 + (size_t)row * D_ + c4 * 4);
    d[0] = __floats2bfloat162_rn(v.x, v.y);
    d[1] = __floats2bfloat162_rn(v.z, v.w);
}

__global__ __launch_bounds__(256) void repack_w3_kernel(const float* __restrict__ W3)
{
    size_t e = (size_t)blockIdx.x * blockDim.x + threadIdx.x;
    if (e >= (size_t)D_ * DFFP2_) return;
    int n = (int)(e / DFFP2_);
    int k = (int)(e - (size_t)n * DFFP2_);
    d_hb[HB_W3P + e] = __float2bfloat16((k < DFF_) ? W3[(size_t)n * DFF_ + k] : 0.f);
}

// ---------------------------------------------------------------------------
// 9. scatter
// ---------------------------------------------------------------------------
__global__ __launch_bounds__(256) void scatter_kernel(float* __restrict__ out)
{
    int row = blockIdx.x;
    int tid = threadIdx.x;
    int b = row >> 9;
    int t = d_idx[row];
    float4 v = ((const float4*)(d_ws + OFF_XPROC + (size_t)row * D_))[tid];
    ((float4*)(out + ((size_t)b * T_ + t) * D_))[tid] = v;
}

// ---------------------------------------------------------------------------
// Launcher
// ---------------------------------------------------------------------------
extern "C" void kernel_launch(void* const* d_in, const int* in_sizes, int n_in,
                              void* d_out, int out_size)
{
    const float* x    = (const float*)d_in[0];
    const float* wr   = (const float*)d_in[1];
    const float* Wqkv = (const float*)d_in[2];
    const float* Wout = (const float*)d_in[3];
    const float* g1   = (const float*)d_in[4];
    const float* g2   = (const float*)d_in[5];
    const float* W1   = (const float*)d_in[6];
    const float* W2   = (const float*)d_in[7];
    const float* W3   = (const float*)d_in[8];
    float* out = (float*)d_out;

    float* ws = nullptr;
    __nv_bfloat16* hb = nullptr;
    cudaGetSymbolAddress((void**)&ws, d_ws);
    cudaGetSymbolAddress((void**)&hb, d_hb);
    cudaFuncSetAttribute(flash_attn_kernel,
                         cudaFuncAttributeMaxDynamicSharedMemorySize, FA_SMEM_BYTES);
    cudaFuncSetAttribute(bf16_gemm_nt,
                         cudaFuncAttributeMaxDynamicSharedMemorySize, G_SMEM_BYTES);

    auto gemm = [&](const __nv_bfloat16* A, const __nv_bfloat16* Bw, void* C,
                    const float* ADD, int M, int N, int K, int ldc, int outBf16) {
        dim3 grid((N + 127) / 128, M / 128);
        bf16_gemm_nt<<<grid, 256, G_SMEM_BYTES>>>(A, Bw, C, ADD, M, N, K, ldc, outBf16);
    };

    // fused copy+router (reads x once), weight prep
    copy_router_kernel<<<B_ * T_, 256>>>(out, x, wr);
    conv_bf16_kernel<<<(int)(((size_t)3 * D_ * D_ / 4 + 255) / 256), 256>>>(
        hb + HB_WQKV, Wqkv, (size_t)3 * D_ * D_ / 4);
    conv_bf16_kernel<<<(int)(((size_t)D_ * D_ / 4 + 255) / 256), 256>>>(
        hb + HB_WOUT, Wout, (size_t)D_ * D_ / 4);
    conv_w12_kernel<<<(int)(((size_t)DFF2_ * D_ / 4 + 255) / 256), 256>>>(W1, W2);
    repack_w3_kernel<<<(int)(((size_t)D_ * DFFP2_ + 255) / 256), 256>>>(W3);

    // routing
    topk_sort512_kernel<<<32, 256>>>();
    topk_merge_kernel<<<B_, 512>>>();

    gather_rmsnorm_kernel<<<M_, 256>>>(x, g1);

    // QKV projection -> bf16
    gemm(hb + HB_H, hb + HB_WQKV, hb + HB_QKV, nullptr, M_, 3 * D_, D_, 3 * D_, 1);

    flash_attn_kernel<<<dim3(B_ * H_, 8), 128, FA_SMEM_BYTES>>>();

    // out projection + residual -> fp32 Y1
    gemm(hb + HB_ATTN, hb + HB_WOUT, ws + OFF_Y1, ws + OFF_XSEL, M_, D_, D_, D_, 0);

    rmsnorm2_kernel<<<M_, 256>>>(g2);

    // fused FFN up (W1|W2) -> bf16 U12
    gemm(hb + HB_H2, hb + HB_W12, hb + HB_U12, nullptr, M_, DFF2_, D_, LD12_, 1);
    swiglu2_kernel<<<(M_ * NPAIR + 255) / 256, 256>>>();

    // FFN down + residual -> fp32 XPROC
    gemm(hb + HB_U, hb + HB_W3P, ws + OFF_XPROC, ws + OFF_Y1, M_, D_, DFFP2_, D_, 0);

    scatter_kernel<<<M_, 256>>>(out);
}